// round 14
// baseline (speedup 1.0000x reference)
#include <cuda_runtime.h>
#include <cuda_bf16.h>
#include <math.h>
#include <stdint.h>

// ---------------- problem constants ----------------
#define HH    56
#define WW    56
#define CH    192
#define TOK   50176        // 16*56*56
#define NHEAD 6
#define HID   768
#define NWIN  1024
#define WSZ   7
#define SHF   3

// ---------------- scratch (device globals, no allocs) ----------------
__device__ __nv_bfloat16 g_xw_h [TOK * CH];
__device__ __nv_bfloat16 g_xw_l [TOK * CH];
__device__ __nv_bfloat16 g_qkv_h[TOK * 3 * CH];
__device__ __nv_bfloat16 g_qkv_l[TOK * 3 * CH];
__device__ __nv_bfloat16 g_ob_h [TOK * CH];
__device__ __nv_bfloat16 g_ob_l [TOK * CH];
__device__ float         g_x1   [TOK * CH];
__device__ __nv_bfloat16 g_hin_h[TOK * CH];
__device__ __nv_bfloat16 g_hin_l[TOK * CH];
__device__ __nv_bfloat16 g_h_h  [TOK * HID];
__device__ __nv_bfloat16 g_h_l  [TOK * HID];
// transposed+split weights, [N, K] row-major
__device__ __nv_bfloat16 g_wqkv_h[3 * CH * CH];
__device__ __nv_bfloat16 g_wqkv_l[3 * CH * CH];
__device__ __nv_bfloat16 g_wprj_h[CH * CH];
__device__ __nv_bfloat16 g_wprj_l[CH * CH];
__device__ __nv_bfloat16 g_wm1_h [HID * CH];
__device__ __nv_bfloat16 g_wm1_l [HID * CH];
__device__ __nv_bfloat16 g_wm2_h [CH * HID];
__device__ __nv_bfloat16 g_wm2_l [CH * HID];

// ---------------- helpers ----------------
__device__ __forceinline__ uint32_t smem_u32(const void* p) {
    uint32_t a;
    asm("{ .reg .u64 t; cvta.to.shared.u64 t, %1; cvt.u32.u64 %0, t; }" : "=r"(a) : "l"(p));
    return a;
}

__device__ __forceinline__ void ldm_x4(uint32_t* r, uint32_t addr) {
    asm volatile("ldmatrix.sync.aligned.m8n8.x4.shared.b16 {%0,%1,%2,%3}, [%4];"
                 : "=r"(r[0]), "=r"(r[1]), "=r"(r[2]), "=r"(r[3]) : "r"(addr));
}

__device__ __forceinline__ void mma_bf16(float* d, const uint32_t* a, uint32_t b0, uint32_t b1) {
    asm volatile("mma.sync.aligned.m16n8k16.row.col.f32.bf16.bf16.f32 "
                 "{%0,%1,%2,%3}, {%4,%5,%6,%7}, {%8,%9}, {%0,%1,%2,%3};"
                 : "+f"(d[0]), "+f"(d[1]), "+f"(d[2]), "+f"(d[3])
                 : "r"(a[0]), "r"(a[1]), "r"(a[2]), "r"(a[3]), "r"(b0), "r"(b1));
}

__device__ __forceinline__ void cp16(uint32_t dst, const void* src) {
    asm volatile("cp.async.cg.shared.global [%0], [%1], 16;" :: "r"(dst), "l"(src));
}

__device__ __forceinline__ void split_store(float v, __nv_bfloat16* ph, __nv_bfloat16* pl) {
    __nv_bfloat16 h = __float2bfloat16(v);
    *ph = h;
    *pl = __float2bfloat16(v - __bfloat162float(h));
}

__device__ __forceinline__ uint32_t pack_bf16(float a, float b) {
    __nv_bfloat162 t(__float2bfloat16(a), __float2bfloat16(b));
    return *reinterpret_cast<uint32_t*>(&t);
}
__device__ __forceinline__ uint32_t pack_bf16_lo(float a, float b, uint32_t hi) {
    __nv_bfloat162 h = *reinterpret_cast<__nv_bfloat162*>(&hi);
    __nv_bfloat162 t(__float2bfloat16(a - __bfloat162float(h.x)),
                     __float2bfloat16(b - __bfloat162float(h.y)));
    return *reinterpret_cast<uint32_t*>(&t);
}

__device__ __forceinline__ int proj_remap(int grow) {
    int win = grow / 49, tt = grow % 49;
    int bb  = win >> 6, rem = win & 63;
    int ii  = (rem >> 3) * WSZ + tt / WSZ;
    int jj  = (rem & 7)  * WSZ + tt % WSZ;
    int yi  = ii + SHF; if (yi >= HH) yi -= HH;
    int xj  = jj + SHF; if (xj >= WW) xj -= WW;
    return (bb * HH + yi) * WW + xj;
}

// ---------------- fused weight prep ----------------
#define WQKV_E (CH * 3 * CH)
#define WPRJ_E (CH * CH)
#define WM1_E  (CH * HID)
#define WM2_E  (HID * CH)
#define WTOT_E (WQKV_E + WPRJ_E + WM1_E + WM2_E)

__global__ void __launch_bounds__(256) wprep_all(
    const float* __restrict__ qkvw, const float* __restrict__ prjw,
    const float* __restrict__ m1w,  const float* __restrict__ m2w,
    __nv_bfloat16* __restrict__ qh, __nv_bfloat16* __restrict__ ql,
    __nv_bfloat16* __restrict__ ph, __nv_bfloat16* __restrict__ pl,
    __nv_bfloat16* __restrict__ h1, __nv_bfloat16* __restrict__ l1,
    __nv_bfloat16* __restrict__ h2, __nv_bfloat16* __restrict__ l2)
{
    int i = blockIdx.x * 256 + threadIdx.x;
    if (i >= WTOT_E) return;
    const float* src; __nv_bfloat16 *dh, *dl; int K, N;
    if (i < WQKV_E)                     { src = qkvw; dh = qh; dl = ql; K = CH;  N = 3 * CH; }
    else if (i < WQKV_E + WPRJ_E)       { i -= WQKV_E;          src = prjw; dh = ph; dl = pl; K = CH;  N = CH; }
    else if (i < WQKV_E + WPRJ_E + WM1_E) { i -= WQKV_E + WPRJ_E; src = m1w;  dh = h1; dl = l1; K = CH;  N = HID; }
    else                                { i -= WQKV_E + WPRJ_E + WM1_E; src = m2w; dh = h2; dl = l2; K = HID; N = CH; }
    int n = i / K, k = i - n * K;
    float v = src[(size_t)k * N + n];
    split_store(v, dh + i, dl + i);
}

// ---------------- LN (warp per row) writing bf16 hi/lo ----------------
template<bool GATHER>
__global__ void __launch_bounds__(256) ln_kernel(const float* __restrict__ x,
                                                 const float* __restrict__ w,
                                                 const float* __restrict__ b,
                                                 __nv_bfloat16* __restrict__ oh,
                                                 __nv_bfloat16* __restrict__ ol)
{
    int row  = (blockIdx.x * blockDim.x + threadIdx.x) >> 5;
    int lane = threadIdx.x & 31;
    if (row >= TOK) return;

    int src_row;
    if (GATHER) {
        int win = row / 49, t = row % 49;
        int bb  = win >> 6, rem = win & 63;
        int i   = (rem >> 3) * WSZ + t / WSZ;
        int j   = (rem & 7)  * WSZ + t % WSZ;
        int yi  = i + SHF; if (yi >= HH) yi -= HH;
        int xj  = j + SHF; if (xj >= WW) xj -= WW;
        src_row = (bb * HH + yi) * WW + xj;
    } else src_row = row;

    const float* px = x + (size_t)src_row * CH;
    float v[6];
    float s = 0.f, s2 = 0.f;
#pragma unroll
    for (int u = 0; u < 6; u++) { v[u] = px[lane + 32 * u]; s += v[u]; s2 += v[u] * v[u]; }
#pragma unroll
    for (int o = 16; o; o >>= 1) {
        s  += __shfl_xor_sync(0xffffffffu, s,  o);
        s2 += __shfl_xor_sync(0xffffffffu, s2, o);
    }
    float mean = s * (1.f / CH);
    float var  = s2 * (1.f / CH) - mean * mean;
    float rstd = rsqrtf(var + 1e-5f);
#pragma unroll
    for (int u = 0; u < 6; u++) {
        int c = lane + 32 * u;
        float val = (v[u] - mean) * rstd * w[c] + b[c];
        split_store(val, oh + (size_t)row * CH + c, ol + (size_t)row * CH + c);
    }
}

// ---------------- GEMM epilogue helper ----------------
enum { EPI_SPLIT = 0, EPI_PROJ = 1, EPI_GELU = 2, EPI_ADD = 3 };

template<int EPI>
__device__ __forceinline__ void epi_store(
    const float* a, int r0, int r1, int col, int NTOT,
    const float* __restrict__ bias,
    float* __restrict__ outf,
    __nv_bfloat16* __restrict__ outh, __nv_bfloat16* __restrict__ outl,
    const float* __restrict__ res, int o0, int o1)
{
    float b0 = bias[col], b1 = bias[col + 1];
    float v0 = a[0] + b0, v1 = a[1] + b1;
    float v2 = a[2] + b0, v3 = a[3] + b1;
    if (EPI == EPI_SPLIT) {
        __nv_bfloat16 h0 = __float2bfloat16(v0), h1 = __float2bfloat16(v1);
        __nv_bfloat16 h2 = __float2bfloat16(v2), h3 = __float2bfloat16(v3);
        *(__nv_bfloat162*)&outh[(size_t)r0 * NTOT + col] = __nv_bfloat162(h0, h1);
        *(__nv_bfloat162*)&outh[(size_t)r1 * NTOT + col] = __nv_bfloat162(h2, h3);
        *(__nv_bfloat162*)&outl[(size_t)r0 * NTOT + col] = __nv_bfloat162(
            __float2bfloat16(v0 - __bfloat162float(h0)), __float2bfloat16(v1 - __bfloat162float(h1)));
        *(__nv_bfloat162*)&outl[(size_t)r1 * NTOT + col] = __nv_bfloat162(
            __float2bfloat16(v2 - __bfloat162float(h2)), __float2bfloat16(v3 - __bfloat162float(h3)));
    } else if (EPI == EPI_PROJ) {
        const float2 s0 = *(const float2*)&res[(size_t)o0 * NTOT + col];
        const float2 s1 = *(const float2*)&res[(size_t)o1 * NTOT + col];
        *(float2*)&outf[(size_t)o0 * NTOT + col] = make_float2(s0.x + v0, s0.y + v1);
        *(float2*)&outf[(size_t)o1 * NTOT + col] = make_float2(s1.x + v2, s1.y + v3);
    } else if (EPI == EPI_GELU) {
        float g0 = 0.5f * v0 * (1.f + erff(v0 * 0.7071067811865475f));
        float g1 = 0.5f * v1 * (1.f + erff(v1 * 0.7071067811865475f));
        float g2 = 0.5f * v2 * (1.f + erff(v2 * 0.7071067811865475f));
        float g3 = 0.5f * v3 * (1.f + erff(v3 * 0.7071067811865475f));
        __nv_bfloat16 h0 = __float2bfloat16(g0), h1 = __float2bfloat16(g1);
        __nv_bfloat16 h2 = __float2bfloat16(g2), h3 = __float2bfloat16(g3);
        *(__nv_bfloat162*)&outh[(size_t)r0 * NTOT + col] = __nv_bfloat162(h0, h1);
        *(__nv_bfloat162*)&outh[(size_t)r1 * NTOT + col] = __nv_bfloat162(h2, h3);
        *(__nv_bfloat162*)&outl[(size_t)r0 * NTOT + col] = __nv_bfloat162(
            __float2bfloat16(g0 - __bfloat162float(h0)), __float2bfloat16(g1 - __bfloat162float(h1)));
        *(__nv_bfloat162*)&outl[(size_t)r1 * NTOT + col] = __nv_bfloat162(
            __float2bfloat16(g2 - __bfloat162float(h2)), __float2bfloat16(g3 - __bfloat162float(h3)));
    } else { // EPI_ADD
        const float2 s0 = *(const float2*)&res[(size_t)r0 * NTOT + col];
        const float2 s1 = *(const float2*)&res[(size_t)r1 * NTOT + col];
        *(float2*)&outf[(size_t)r0 * NTOT + col] = make_float2(s0.x + v0, s0.y + v1);
        *(float2*)&outf[(size_t)r1 * NTOT + col] = make_float2(s1.x + v2, s1.y + v3);
    }
}

// ---------------- tgemm64: M=128 x N=64, K-chunk 64, 2 CTA/SM (R11 config) ----------------
#define KP   72
#define STG_AH 0u
#define STG_AL 18432u
#define STG_BH 36864u
#define STG_BL 46080u
#define STG_BYTES 55296u
#define SMEM_DYN64 (2 * 55296)

template<int EPI, int NTOT, int KTOT>
__global__ void __launch_bounds__(256) tgemm64(
    const __nv_bfloat16* __restrict__ Ah, const __nv_bfloat16* __restrict__ Al,
    const __nv_bfloat16* __restrict__ Bh, const __nv_bfloat16* __restrict__ Bl,
    const float* __restrict__ bias,
    float* __restrict__ outf,
    __nv_bfloat16* __restrict__ outh, __nv_bfloat16* __restrict__ outl,
    const float* __restrict__ res)
{
    extern __shared__ __nv_bfloat16 S[];
    const uint32_t sbase = smem_u32(S);

    const int tid  = threadIdx.x;
    const int lane = tid & 31, wid = tid >> 5;
    const int wm   = wid & 3,  wn  = wid >> 2;
    const int n0   = blockIdx.x * 64;
    const int m0   = blockIdx.y * 128;

    const uint32_t aOff = (uint32_t)((wm * 32 + (lane & 15)) * KP + (lane >> 4) * 8) * 2;
    const uint32_t bOff = (uint32_t)((wn * 32 + (lane & 7) + ((lane >> 4) << 3)) * KP + ((lane >> 3) & 1) * 8) * 2;

    float acc[2][4][4];
#pragma unroll
    for (int i = 0; i < 2; i++)
#pragma unroll
        for (int j = 0; j < 4; j++)
#pragma unroll
            for (int q = 0; q < 4; q++) acc[i][j][q] = 0.f;

    const int KCH = KTOT / 64;

    auto issue = [&](int kc) {
        const uint32_t so = sbase + (uint32_t)(kc & 1) * STG_BYTES;
        const size_t abase = (size_t)m0 * KTOT + (size_t)kc * 64;
        const size_t bbase = (size_t)n0 * KTOT + (size_t)kc * 64;
#pragma unroll
        for (int i = tid; i < 128 * 8; i += 256) {
            int r = i >> 3, c = i & 7;
            uint32_t d = so + (uint32_t)(r * KP + c * 8) * 2;
            const size_t g = abase + (size_t)r * KTOT + c * 8;
            cp16(d + STG_AH, Ah + g);
            cp16(d + STG_AL, Al + g);
        }
#pragma unroll
        for (int i = tid; i < 64 * 8; i += 256) {
            int r = i >> 3, c = i & 7;
            uint32_t d = so + (uint32_t)(r * KP + c * 8) * 2;
            const size_t g = bbase + (size_t)r * KTOT + c * 8;
            cp16(d + STG_BH, Bh + g);
            cp16(d + STG_BL, Bl + g);
        }
        asm volatile("cp.async.commit_group;" ::: "memory");
    };

    issue(0);

    for (int kc = 0; kc < KCH; kc++) {
        if (kc + 1 < KCH) {
            issue(kc + 1);
            asm volatile("cp.async.wait_group 1;" ::: "memory");
        } else {
            asm volatile("cp.async.wait_group 0;" ::: "memory");
        }
        __syncthreads();

        const uint32_t so = sbase + (uint32_t)(kc & 1) * STG_BYTES;
        const uint32_t adrAh0 = so + STG_AH + aOff, adrAh1 = adrAh0 + 16 * KP * 2;
        const uint32_t adrAl0 = so + STG_AL + aOff, adrAl1 = adrAl0 + 16 * KP * 2;
        const uint32_t adrBh0 = so + STG_BH + bOff, adrBh1 = adrBh0 + 16 * KP * 2;
        const uint32_t adrBl0 = so + STG_BL + bOff, adrBl1 = adrBl0 + 16 * KP * 2;

#pragma unroll
        for (int ks = 0; ks < 4; ks++) {
            const uint32_t kb = (uint32_t)(ks * 32);
            uint32_t ah0[4], ah1[4], al0[4], al1[4];
            uint32_t bh0[4], bh1[4], bl0[4], bl1[4];
            ldm_x4(ah0, adrAh0 + kb);
            ldm_x4(ah1, adrAh1 + kb);
            ldm_x4(al0, adrAl0 + kb);
            ldm_x4(al1, adrAl1 + kb);
            ldm_x4(bh0, adrBh0 + kb);
            ldm_x4(bh1, adrBh1 + kb);
            ldm_x4(bl0, adrBl0 + kb);
            ldm_x4(bl1, adrBl1 + kb);

#pragma unroll
            for (int nt = 0; nt < 4; nt++) {
                uint32_t h0 = (nt < 2 ? bh0[(nt & 1) * 2]     : bh1[(nt & 1) * 2]);
                uint32_t h1 = (nt < 2 ? bh0[(nt & 1) * 2 + 1] : bh1[(nt & 1) * 2 + 1]);
                uint32_t l0 = (nt < 2 ? bl0[(nt & 1) * 2]     : bl1[(nt & 1) * 2]);
                uint32_t l1 = (nt < 2 ? bl0[(nt & 1) * 2 + 1] : bl1[(nt & 1) * 2 + 1]);
                mma_bf16(acc[0][nt], ah0, h0, h1);
                mma_bf16(acc[1][nt], ah1, h0, h1);
                mma_bf16(acc[0][nt], ah0, l0, l1);
                mma_bf16(acc[1][nt], ah1, l0, l1);
                mma_bf16(acc[0][nt], al0, h0, h1);
                mma_bf16(acc[1][nt], al1, h0, h1);
            }
        }
        __syncthreads();
    }

    const int g = lane >> 2, t4 = lane & 3;
#pragma unroll
    for (int mt = 0; mt < 2; mt++) {
        int r0 = m0 + wm * 32 + mt * 16 + g;
        int r1 = r0 + 8;
        int o0 = r0, o1 = r1;
        if (EPI == EPI_PROJ) { o0 = proj_remap(r0); o1 = proj_remap(r1); }
#pragma unroll
        for (int nt = 0; nt < 4; nt++) {
            int col = n0 + wn * 32 + nt * 8 + 2 * t4;
            epi_store<EPI>(acc[mt][nt], r0, r1, col, NTOT, bias, outf, outh, outl, res, o0, o1);
        }
    }
}

// ---------------- attention v5: register-P (R11) + split-bf16 qkv inputs ----------------
#define QKP 40
#define VTP 72
#define AQH 0u
#define AQL 5120u
#define AKH 10240u
#define AKL 15360u
#define AVH 20480u
#define AVL 25088u
#define ATTN_SMEM 29696

__global__ void __launch_bounds__(128) attn_mma()
{
    extern __shared__ __align__(16) char SM[];
    __nv_bfloat16* sQh = (__nv_bfloat16*)(SM + AQH);
    __nv_bfloat16* sQl = (__nv_bfloat16*)(SM + AQL);
    __nv_bfloat16* sKh = (__nv_bfloat16*)(SM + AKH);
    __nv_bfloat16* sKl = (__nv_bfloat16*)(SM + AKL);
    __nv_bfloat16* sVh = (__nv_bfloat16*)(SM + AVH);
    __nv_bfloat16* sVl = (__nv_bfloat16*)(SM + AVL);

    const int win = blockIdx.x / NHEAD;
    const int h   = blockIdx.x % NHEAD;
    const int tid = threadIdx.x;
    const int lane = tid & 31, w = tid >> 5;

    // ---- zero pads: Q/K rows 49..63; VT cols 49..63 ----
    for (int i = tid; i < 15 * 32; i += 128) {
        int r = 49 + (i >> 5), c = i & 31;
        sQh[r * QKP + c] = __nv_bfloat16(0.f);
        sQl[r * QKP + c] = __nv_bfloat16(0.f);
        sKh[r * QKP + c] = __nv_bfloat16(0.f);
        sKl[r * QKP + c] = __nv_bfloat16(0.f);
    }
    for (int i = tid; i < 32 * 15; i += 128) {
        int d = i / 15, j = 49 + i % 15;
        sVh[d * VTP + j] = __nv_bfloat16(0.f);
        sVl[d * VTP + j] = __nv_bfloat16(0.f);
    }

    // ---- stage q,k (vector copies) and v (transpose) from split-bf16 qkv ----
    const __nv_bfloat16* bqh = g_qkv_h + (size_t)win * 49 * (3 * CH) + h * 32;
    const __nv_bfloat16* bql = g_qkv_l + (size_t)win * 49 * (3 * CH) + h * 32;
    for (int i = tid; i < 49 * 4; i += 128) {
        int r = i >> 2, c = i & 3;
        const size_t go = (size_t)r * (3 * CH) + c * 8;
        *(uint4*)&sQh[r * QKP + c * 8] = *(const uint4*)&bqh[go];
        *(uint4*)&sQl[r * QKP + c * 8] = *(const uint4*)&bql[go];
        *(uint4*)&sKh[r * QKP + c * 8] = *(const uint4*)&bqh[go + CH];
        *(uint4*)&sKl[r * QKP + c * 8] = *(const uint4*)&bql[go + CH];
    }
    for (int i = tid; i < 49 * 32; i += 128) {
        int t = i >> 5, d = i & 31;
        const size_t go = (size_t)t * (3 * CH) + 2 * CH + d;
        sVh[d * VTP + t] = bqh[go];
        sVl[d * VTP + t] = bql[go];
    }
    __syncthreads();   // the ONLY block-wide sync

    const uint32_t sb = smem_u32(SM);
    const int g = lane >> 2, t4 = lane & 3;
    const int r0 = w * 16 + g, r1 = r0 + 8;

    // ---- QK^T: warp w -> score rows r0,r1 over cols 0..63, in registers ----
    float acc[8][4];
#pragma unroll
    for (int i = 0; i < 8; i++)
#pragma unroll
        for (int j = 0; j < 4; j++) acc[i][j] = 0.f;

    {
        const uint32_t aoff = (uint32_t)((w * 16 + (lane & 15)) * QKP + (lane >> 4) * 8) * 2;
        const uint32_t adrQh = sb + AQH + aoff;
        const uint32_t adrQl = sb + AQL + aoff;
        const uint32_t brow  = (uint32_t)((lane & 7) + ((lane >> 4) << 3));
        const uint32_t bcol  = (uint32_t)(((lane >> 3) & 1) * 8);

#pragma unroll
        for (int ks = 0; ks < 2; ks++) {
            const uint32_t kb = (uint32_t)(ks * 32);
            uint32_t qh[4], ql[4];
            ldm_x4(qh, adrQh + kb);
            ldm_x4(ql, adrQl + kb);
#pragma unroll
            for (int nb = 0; nb < 4; nb++) {
                const uint32_t boff = (uint32_t)((nb * 16 + brow) * QKP + bcol) * 2 + kb;
                uint32_t kh[4], kl[4];
                ldm_x4(kh, sb + AKH + boff);
                ldm_x4(kl, sb + AKL + boff);
#pragma unroll
                for (int s = 0; s < 2; s++) {
                    int nt = nb * 2 + s;
                    mma_bf16(acc[nt], qh, kh[s * 2], kh[s * 2 + 1]);
                    mma_bf16(acc[nt], qh, kl[s * 2], kl[s * 2 + 1]);
                    mma_bf16(acc[nt], ql, kh[s * 2], kh[s * 2 + 1]);
                }
            }
        }
    }

    // ---- scale scores (reference order: matmul then scale) ----
    const float scale = 0.17677669529663687f;
#pragma unroll
    for (int nt = 0; nt < 8; nt++)
#pragma unroll
        for (int j = 0; j < 4; j++) acc[nt][j] *= scale;

    // ---- register softmax over rows r0 (acc[][0..1]) and r1 (acc[][2..3]) ----
    {
        float mx0 = -1e30f, mx1 = -1e30f;
#pragma unroll
        for (int nt = 0; nt < 8; nt++) {
            int col = nt * 8 + 2 * t4;
            if (col < 49)     { mx0 = fmaxf(mx0, acc[nt][0]); mx1 = fmaxf(mx1, acc[nt][2]); }
            if (col + 1 < 49) { mx0 = fmaxf(mx0, acc[nt][1]); mx1 = fmaxf(mx1, acc[nt][3]); }
        }
        mx0 = fmaxf(mx0, __shfl_xor_sync(0xffffffffu, mx0, 1));
        mx0 = fmaxf(mx0, __shfl_xor_sync(0xffffffffu, mx0, 2));
        mx1 = fmaxf(mx1, __shfl_xor_sync(0xffffffffu, mx1, 1));
        mx1 = fmaxf(mx1, __shfl_xor_sync(0xffffffffu, mx1, 2));

        float s0 = 0.f, s1 = 0.f;
#pragma unroll
        for (int nt = 0; nt < 8; nt++) {
            int col = nt * 8 + 2 * t4;
            float e0 = (col < 49)     ? expf(acc[nt][0] - mx0) : 0.f;
            float e1 = (col + 1 < 49) ? expf(acc[nt][1] - mx0) : 0.f;
            float e2 = (col < 49)     ? expf(acc[nt][2] - mx1) : 0.f;
            float e3 = (col + 1 < 49) ? expf(acc[nt][3] - mx1) : 0.f;
            acc[nt][0] = e0; acc[nt][1] = e1; acc[nt][2] = e2; acc[nt][3] = e3;
            s0 += e0 + e1; s1 += e2 + e3;
        }
        s0 += __shfl_xor_sync(0xffffffffu, s0, 1);
        s0 += __shfl_xor_sync(0xffffffffu, s0, 2);
        s1 += __shfl_xor_sync(0xffffffffu, s1, 1);
        s1 += __shfl_xor_sync(0xffffffffu, s1, 2);
        float inv0 = 1.f / s0, inv1 = 1.f / s1;

#pragma unroll
        for (int nt = 0; nt < 8; nt++) {
            acc[nt][0] *= inv0; acc[nt][1] *= inv0;
            acc[nt][2] *= inv1; acc[nt][3] *= inv1;
        }
    }

    // ---- AV: P consumed directly from registers ----
    {
        const uint32_t brow = (uint32_t)((lane & 7) + ((lane >> 4) << 3));
        const uint32_t bcol = (uint32_t)(((lane >> 3) & 1) * 8);

        float oacc[4][4];
#pragma unroll
        for (int i = 0; i < 4; i++)
#pragma unroll
            for (int j = 0; j < 4; j++) oacc[i][j] = 0.f;

#pragma unroll
        for (int ks = 0; ks < 4; ks++) {
            uint32_t ph[4], pl[4];
            ph[0] = pack_bf16(acc[2 * ks][0],     acc[2 * ks][1]);
            ph[1] = pack_bf16(acc[2 * ks][2],     acc[2 * ks][3]);
            ph[2] = pack_bf16(acc[2 * ks + 1][0], acc[2 * ks + 1][1]);
            ph[3] = pack_bf16(acc[2 * ks + 1][2], acc[2 * ks + 1][3]);
            pl[0] = pack_bf16_lo(acc[2 * ks][0],     acc[2 * ks][1],     ph[0]);
            pl[1] = pack_bf16_lo(acc[2 * ks][2],     acc[2 * ks][3],     ph[1]);
            pl[2] = pack_bf16_lo(acc[2 * ks + 1][0], acc[2 * ks + 1][1], ph[2]);
            pl[3] = pack_bf16_lo(acc[2 * ks + 1][2], acc[2 * ks + 1][3], ph[3]);

            const uint32_t kb = (uint32_t)(ks * 32);
#pragma unroll
            for (int nb = 0; nb < 2; nb++) {
                const uint32_t boff = (uint32_t)((nb * 16 + brow) * VTP + bcol) * 2 + kb;
                uint32_t vh[4], vl[4];
                ldm_x4(vh, sb + AVH + boff);
                ldm_x4(vl, sb + AVL + boff);
#pragma unroll
                for (int s = 0; s < 2; s++) {
                    int nt = nb * 2 + s;
                    mma_bf16(oacc[nt], ph, vh[s * 2], vh[s * 2 + 1]);
                    mma_bf16(oacc[nt], ph, vl[s * 2], vl[s * 2 + 1]);
                    mma_bf16(oacc[nt], pl, vh[s * 2], vh[s * 2 + 1]);
                }
            }
        }

        const size_t ob = (size_t)win * 49 * CH + h * 32;
#pragma unroll
        for (int nt = 0; nt < 4; nt++) {
            int d = nt * 8 + t4 * 2;
            if (r0 < 49) {
                float v0 = oacc[nt][0], v1 = oacc[nt][1];
                __nv_bfloat16 h0 = __float2bfloat16(v0), h1 = __float2bfloat16(v1);
                *(__nv_bfloat162*)&g_ob_h[ob + (size_t)r0 * CH + d] = __nv_bfloat162(h0, h1);
                *(__nv_bfloat162*)&g_ob_l[ob + (size_t)r0 * CH + d] = __nv_bfloat162(
                    __float2bfloat16(v0 - __bfloat162float(h0)), __float2bfloat16(v1 - __bfloat162float(h1)));
            }
            if (r1 < 49) {
                float v2 = oacc[nt][2], v3 = oacc[nt][3];
                __nv_bfloat16 h2 = __float2bfloat16(v2), h3 = __float2bfloat16(v3);
                *(__nv_bfloat162*)&g_ob_h[ob + (size_t)r1 * CH + d] = __nv_bfloat162(h2, h3);
                *(__nv_bfloat162*)&g_ob_l[ob + (size_t)r1 * CH + d] = __nv_bfloat162(
                    __float2bfloat16(v2 - __bfloat162float(h2)), __float2bfloat16(v3 - __bfloat162float(h3)));
            }
        }
    }
}

// ---------------- launch ----------------
extern "C" void kernel_launch(void* const* d_in, const int* in_sizes, int n_in,
                              void* d_out, int out_size)
{
    const float* x      = (const float*)d_in[0];
    const float* ln1_w  = (const float*)d_in[1];
    const float* ln1_b  = (const float*)d_in[2];
    const float* qkv_w  = (const float*)d_in[3];
    const float* qkv_b  = (const float*)d_in[4];
    const float* proj_w = (const float*)d_in[5];
    const float* proj_b = (const float*)d_in[6];
    const float* ln2_w  = (const float*)d_in[7];
    const float* ln2_b  = (const float*)d_in[8];
    const float* mlp_w1 = (const float*)d_in[9];
    const float* mlp_b1 = (const float*)d_in[10];
    const float* mlp_w2 = (const float*)d_in[11];
    const float* mlp_b2 = (const float*)d_in[12];
    float* out = (float*)d_out;

    float *p_x1;
    __nv_bfloat16 *p_xw_h, *p_xw_l, *p_qkv_h, *p_qkv_l, *p_ob_h, *p_ob_l, *p_hin_h, *p_hin_l, *p_h_h, *p_h_l;
    __nv_bfloat16 *p_wqkv_h, *p_wqkv_l, *p_wprj_h, *p_wprj_l, *p_wm1_h, *p_wm1_l, *p_wm2_h, *p_wm2_l;
    cudaGetSymbolAddress((void**)&p_x1,     g_x1);
    cudaGetSymbolAddress((void**)&p_xw_h,   g_xw_h);
    cudaGetSymbolAddress((void**)&p_xw_l,   g_xw_l);
    cudaGetSymbolAddress((void**)&p_qkv_h,  g_qkv_h);
    cudaGetSymbolAddress((void**)&p_qkv_l,  g_qkv_l);
    cudaGetSymbolAddress((void**)&p_ob_h,   g_ob_h);
    cudaGetSymbolAddress((void**)&p_ob_l,   g_ob_l);
    cudaGetSymbolAddress((void**)&p_hin_h,  g_hin_h);
    cudaGetSymbolAddress((void**)&p_hin_l,  g_hin_l);
    cudaGetSymbolAddress((void**)&p_h_h,    g_h_h);
    cudaGetSymbolAddress((void**)&p_h_l,    g_h_l);
    cudaGetSymbolAddress((void**)&p_wqkv_h, g_wqkv_h);
    cudaGetSymbolAddress((void**)&p_wqkv_l, g_wqkv_l);
    cudaGetSymbolAddress((void**)&p_wprj_h, g_wprj_h);
    cudaGetSymbolAddress((void**)&p_wprj_l, g_wprj_l);
    cudaGetSymbolAddress((void**)&p_wm1_h,  g_wm1_h);
    cudaGetSymbolAddress((void**)&p_wm1_l,  g_wm1_l);
    cudaGetSymbolAddress((void**)&p_wm2_h,  g_wm2_h);
    cudaGetSymbolAddress((void**)&p_wm2_l,  g_wm2_l);

    cudaFuncSetAttribute(tgemm64<EPI_SPLIT, 576, 192>, cudaFuncAttributeMaxDynamicSharedMemorySize, SMEM_DYN64);
    cudaFuncSetAttribute(tgemm64<EPI_PROJ, 192, 192>,  cudaFuncAttributeMaxDynamicSharedMemorySize, SMEM_DYN64);
    cudaFuncSetAttribute(tgemm64<EPI_GELU, 768, 192>,  cudaFuncAttributeMaxDynamicSharedMemorySize, SMEM_DYN64);
    cudaFuncSetAttribute(tgemm64<EPI_ADD, 192, 768>,   cudaFuncAttributeMaxDynamicSharedMemorySize, SMEM_DYN64);
    cudaFuncSetAttribute(attn_mma, cudaFuncAttributeMaxDynamicSharedMemorySize, ATTN_SMEM);

    wprep_all<<<(WTOT_E + 255) / 256, 256>>>(qkv_w, proj_w, mlp_w1, mlp_w2,
                                             p_wqkv_h, p_wqkv_l, p_wprj_h, p_wprj_l,
                                             p_wm1_h, p_wm1_l, p_wm2_h, p_wm2_l);

    const int LN_BLOCKS = TOK / 8;

    // 1. LN1 + shift + window partition
    ln_kernel<true><<<LN_BLOCKS, 256>>>(x, ln1_w, ln1_b, p_xw_h, p_xw_l);

    // 2. qkv GEMM -> split bf16 (saves 153MB of fp32 round-trip)
    tgemm64<EPI_SPLIT, 576, 192><<<dim3(9, TOK / 128), 256, SMEM_DYN64>>>(
        p_xw_h, p_xw_l, p_wqkv_h, p_wqkv_l, qkv_b, nullptr, p_qkv_h, p_qkv_l, nullptr);

    // 3. windowed attention (register-P, bf16 inputs)
    attn_mma<<<NWIN * NHEAD, 128, ATTN_SMEM>>>();

    // 4. proj GEMM + window reverse + unshift + shortcut
    tgemm64<EPI_PROJ, 192, 192><<<dim3(3, TOK / 128), 256, SMEM_DYN64>>>(
        p_ob_h, p_ob_l, p_wprj_h, p_wprj_l, proj_b, p_x1, nullptr, nullptr, x);

    // 5. LN2
    ln_kernel<false><<<LN_BLOCKS, 256>>>(p_x1, ln2_w, ln2_b, p_hin_h, p_hin_l);

    // 6. mlp1 + GELU
    tgemm64<EPI_GELU, 768, 192><<<dim3(12, TOK / 128), 256, SMEM_DYN64>>>(
        p_hin_h, p_hin_l, p_wm1_h, p_wm1_l, mlp_b1, nullptr, p_h_h, p_h_l, nullptr);

    // 7. mlp2 + residual
    tgemm64<EPI_ADD, 192, 768><<<dim3(3, TOK / 128), 256, SMEM_DYN64>>>(
        p_h_h, p_h_l, p_wm2_h, p_wm2_l, mlp_b2, out, nullptr, nullptr, p_x1);
}

// round 15
// speedup vs baseline: 1.0442x; 1.0442x over previous
#include <cuda_runtime.h>
#include <cuda_bf16.h>
#include <math.h>
#include <stdint.h>

// ---------------- problem constants ----------------
#define HH    56
#define WW    56
#define CH    192
#define TOK   50176        // 16*56*56
#define NHEAD 6
#define HID   768
#define NWIN  1024
#define WSZ   7
#define SHF   3

// ---------------- scratch (device globals, no allocs) ----------------
__device__ __nv_bfloat16 g_xw_h [TOK * CH];
__device__ __nv_bfloat16 g_xw_l [TOK * CH];
__device__ float         g_qkv  [TOK * 3 * CH];
__device__ __nv_bfloat16 g_ob_h [TOK * CH];
__device__ __nv_bfloat16 g_ob_l [TOK * CH];
__device__ float         g_x1   [TOK * CH];
__device__ __nv_bfloat16 g_hin_h[TOK * CH];
__device__ __nv_bfloat16 g_hin_l[TOK * CH];
__device__ __nv_bfloat16 g_h_h  [TOK * HID];
__device__ __nv_bfloat16 g_h_l  [TOK * HID];
// transposed+split weights, [N, K] row-major
__device__ __nv_bfloat16 g_wqkv_h[3 * CH * CH];
__device__ __nv_bfloat16 g_wqkv_l[3 * CH * CH];
__device__ __nv_bfloat16 g_wprj_h[CH * CH];
__device__ __nv_bfloat16 g_wprj_l[CH * CH];
__device__ __nv_bfloat16 g_wm1_h [HID * CH];
__device__ __nv_bfloat16 g_wm1_l [HID * CH];
__device__ __nv_bfloat16 g_wm2_h [CH * HID];
__device__ __nv_bfloat16 g_wm2_l [CH * HID];

// ---------------- helpers ----------------
__device__ __forceinline__ uint32_t smem_u32(const void* p) {
    uint32_t a;
    asm("{ .reg .u64 t; cvta.to.shared.u64 t, %1; cvt.u32.u64 %0, t; }" : "=r"(a) : "l"(p));
    return a;
}

__device__ __forceinline__ void ldm_x4(uint32_t* r, uint32_t addr) {
    asm volatile("ldmatrix.sync.aligned.m8n8.x4.shared.b16 {%0,%1,%2,%3}, [%4];"
                 : "=r"(r[0]), "=r"(r[1]), "=r"(r[2]), "=r"(r[3]) : "r"(addr));
}

__device__ __forceinline__ void mma_bf16(float* d, const uint32_t* a, uint32_t b0, uint32_t b1) {
    asm volatile("mma.sync.aligned.m16n8k16.row.col.f32.bf16.bf16.f32 "
                 "{%0,%1,%2,%3}, {%4,%5,%6,%7}, {%8,%9}, {%0,%1,%2,%3};"
                 : "+f"(d[0]), "+f"(d[1]), "+f"(d[2]), "+f"(d[3])
                 : "r"(a[0]), "r"(a[1]), "r"(a[2]), "r"(a[3]), "r"(b0), "r"(b1));
}

__device__ __forceinline__ void cp16(uint32_t dst, const void* src) {
    asm volatile("cp.async.cg.shared.global [%0], [%1], 16;" :: "r"(dst), "l"(src));
}

__device__ __forceinline__ void split_store(float v, __nv_bfloat16* ph, __nv_bfloat16* pl) {
    __nv_bfloat16 h = __float2bfloat16(v);
    *ph = h;
    *pl = __float2bfloat16(v - __bfloat162float(h));
}

__device__ __forceinline__ uint32_t pack_bf16(float a, float b) {
    __nv_bfloat162 t(__float2bfloat16(a), __float2bfloat16(b));
    return *reinterpret_cast<uint32_t*>(&t);
}
__device__ __forceinline__ uint32_t pack_bf16_lo(float a, float b, uint32_t hi) {
    __nv_bfloat162 h = *reinterpret_cast<__nv_bfloat162*>(&hi);
    __nv_bfloat162 t(__float2bfloat16(a - __bfloat162float(h.x)),
                     __float2bfloat16(b - __bfloat162float(h.y)));
    return *reinterpret_cast<uint32_t*>(&t);
}

__device__ __forceinline__ int proj_remap(int grow) {
    int win = grow / 49, tt = grow % 49;
    int bb  = win >> 6, rem = win & 63;
    int ii  = (rem >> 3) * WSZ + tt / WSZ;
    int jj  = (rem & 7)  * WSZ + tt % WSZ;
    int yi  = ii + SHF; if (yi >= HH) yi -= HH;
    int xj  = jj + SHF; if (xj >= WW) xj -= WW;
    return (bb * HH + yi) * WW + xj;
}

// ---------------- fused weight prep ----------------
#define WQKV_E (CH * 3 * CH)
#define WPRJ_E (CH * CH)
#define WM1_E  (CH * HID)
#define WM2_E  (HID * CH)
#define WTOT_E (WQKV_E + WPRJ_E + WM1_E + WM2_E)

__global__ void __launch_bounds__(256) wprep_all(
    const float* __restrict__ qkvw, const float* __restrict__ prjw,
    const float* __restrict__ m1w,  const float* __restrict__ m2w,
    __nv_bfloat16* __restrict__ qh, __nv_bfloat16* __restrict__ ql,
    __nv_bfloat16* __restrict__ ph, __nv_bfloat16* __restrict__ pl,
    __nv_bfloat16* __restrict__ h1, __nv_bfloat16* __restrict__ l1,
    __nv_bfloat16* __restrict__ h2, __nv_bfloat16* __restrict__ l2)
{
    int i = blockIdx.x * 256 + threadIdx.x;
    if (i >= WTOT_E) return;
    const float* src; __nv_bfloat16 *dh, *dl; int K, N;
    if (i < WQKV_E)                     { src = qkvw; dh = qh; dl = ql; K = CH;  N = 3 * CH; }
    else if (i < WQKV_E + WPRJ_E)       { i -= WQKV_E;          src = prjw; dh = ph; dl = pl; K = CH;  N = CH; }
    else if (i < WQKV_E + WPRJ_E + WM1_E) { i -= WQKV_E + WPRJ_E; src = m1w;  dh = h1; dl = l1; K = CH;  N = HID; }
    else                                { i -= WQKV_E + WPRJ_E + WM1_E; src = m2w; dh = h2; dl = l2; K = HID; N = CH; }
    int n = i / K, k = i - n * K;
    float v = src[(size_t)k * N + n];
    split_store(v, dh + i, dl + i);
}

// ---------------- LN (warp per row) writing bf16 hi/lo ----------------
template<bool GATHER>
__global__ void __launch_bounds__(256) ln_kernel(const float* __restrict__ x,
                                                 const float* __restrict__ w,
                                                 const float* __restrict__ b,
                                                 __nv_bfloat16* __restrict__ oh,
                                                 __nv_bfloat16* __restrict__ ol)
{
    int row  = (blockIdx.x * blockDim.x + threadIdx.x) >> 5;
    int lane = threadIdx.x & 31;
    if (row >= TOK) return;

    int src_row;
    if (GATHER) {
        int win = row / 49, t = row % 49;
        int bb  = win >> 6, rem = win & 63;
        int i   = (rem >> 3) * WSZ + t / WSZ;
        int j   = (rem & 7)  * WSZ + t % WSZ;
        int yi  = i + SHF; if (yi >= HH) yi -= HH;
        int xj  = j + SHF; if (xj >= WW) xj -= WW;
        src_row = (bb * HH + yi) * WW + xj;
    } else src_row = row;

    const float* px = x + (size_t)src_row * CH;
    float v[6];
    float s = 0.f, s2 = 0.f;
#pragma unroll
    for (int u = 0; u < 6; u++) { v[u] = px[lane + 32 * u]; s += v[u]; s2 += v[u] * v[u]; }
#pragma unroll
    for (int o = 16; o; o >>= 1) {
        s  += __shfl_xor_sync(0xffffffffu, s,  o);
        s2 += __shfl_xor_sync(0xffffffffu, s2, o);
    }
    float mean = s * (1.f / CH);
    float var  = s2 * (1.f / CH) - mean * mean;
    float rstd = rsqrtf(var + 1e-5f);
#pragma unroll
    for (int u = 0; u < 6; u++) {
        int c = lane + 32 * u;
        float val = (v[u] - mean) * rstd * w[c] + b[c];
        split_store(val, oh + (size_t)row * CH + c, ol + (size_t)row * CH + c);
    }
}

// ---------------- mma.sync split-bf16 GEMM (R11 config, unchanged) ----------------
enum { EPI_QKV = 0, EPI_PROJ = 1, EPI_GELU = 2, EPI_ADD = 3 };

#define KP   72
#define STG_AH 0u
#define STG_AL 18432u
#define STG_BH 36864u
#define STG_BL 46080u
#define STG_BYTES 55296u
#define SMEM_DYN (2 * 55296)

template<int EPI, int NTOT, int KTOT>
__global__ void __launch_bounds__(256) tgemm(
    const __nv_bfloat16* __restrict__ Ah, const __nv_bfloat16* __restrict__ Al,
    const __nv_bfloat16* __restrict__ Bh, const __nv_bfloat16* __restrict__ Bl,
    const float* __restrict__ bias,
    float* __restrict__ outf,
    __nv_bfloat16* __restrict__ outh, __nv_bfloat16* __restrict__ outl,
    const float* __restrict__ res)
{
    extern __shared__ __nv_bfloat16 S[];
    const uint32_t sbase = smem_u32(S);

    const int tid  = threadIdx.x;
    const int lane = tid & 31, wid = tid >> 5;
    const int wm   = wid & 3,  wn  = wid >> 2;
    const int n0   = blockIdx.x * 64;
    const int m0   = blockIdx.y * 128;

    const uint32_t aOff = (uint32_t)((wm * 32 + (lane & 15)) * KP + (lane >> 4) * 8) * 2;
    const uint32_t bOff = (uint32_t)((wn * 32 + (lane & 7) + ((lane >> 4) << 3)) * KP + ((lane >> 3) & 1) * 8) * 2;

    float acc[2][4][4];
#pragma unroll
    for (int i = 0; i < 2; i++)
#pragma unroll
        for (int j = 0; j < 4; j++)
#pragma unroll
            for (int q = 0; q < 4; q++) acc[i][j][q] = 0.f;

    const int KCH = KTOT / 64;

    auto issue = [&](int kc) {
        const uint32_t so = sbase + (uint32_t)(kc & 1) * STG_BYTES;
        const size_t abase = (size_t)m0 * KTOT + (size_t)kc * 64;
        const size_t bbase = (size_t)n0 * KTOT + (size_t)kc * 64;
#pragma unroll
        for (int i = tid; i < 128 * 8; i += 256) {
            int r = i >> 3, c = i & 7;
            uint32_t d = so + (uint32_t)(r * KP + c * 8) * 2;
            const size_t g = abase + (size_t)r * KTOT + c * 8;
            cp16(d + STG_AH, Ah + g);
            cp16(d + STG_AL, Al + g);
        }
#pragma unroll
        for (int i = tid; i < 64 * 8; i += 256) {
            int r = i >> 3, c = i & 7;
            uint32_t d = so + (uint32_t)(r * KP + c * 8) * 2;
            const size_t g = bbase + (size_t)r * KTOT + c * 8;
            cp16(d + STG_BH, Bh + g);
            cp16(d + STG_BL, Bl + g);
        }
        asm volatile("cp.async.commit_group;" ::: "memory");
    };

    issue(0);

    for (int kc = 0; kc < KCH; kc++) {
        if (kc + 1 < KCH) {
            issue(kc + 1);
            asm volatile("cp.async.wait_group 1;" ::: "memory");
        } else {
            asm volatile("cp.async.wait_group 0;" ::: "memory");
        }
        __syncthreads();

        const uint32_t so = sbase + (uint32_t)(kc & 1) * STG_BYTES;
        const uint32_t adrAh0 = so + STG_AH + aOff, adrAh1 = adrAh0 + 16 * KP * 2;
        const uint32_t adrAl0 = so + STG_AL + aOff, adrAl1 = adrAl0 + 16 * KP * 2;
        const uint32_t adrBh0 = so + STG_BH + bOff, adrBh1 = adrBh0 + 16 * KP * 2;
        const uint32_t adrBl0 = so + STG_BL + bOff, adrBl1 = adrBl0 + 16 * KP * 2;

#pragma unroll
        for (int ks = 0; ks < 4; ks++) {
            const uint32_t kb = (uint32_t)(ks * 32);
            uint32_t ah0[4], ah1[4], al0[4], al1[4];
            uint32_t bh0[4], bh1[4], bl0[4], bl1[4];
            ldm_x4(ah0, adrAh0 + kb);
            ldm_x4(ah1, adrAh1 + kb);
            ldm_x4(al0, adrAl0 + kb);
            ldm_x4(al1, adrAl1 + kb);
            ldm_x4(bh0, adrBh0 + kb);
            ldm_x4(bh1, adrBh1 + kb);
            ldm_x4(bl0, adrBl0 + kb);
            ldm_x4(bl1, adrBl1 + kb);

#pragma unroll
            for (int nt = 0; nt < 4; nt++) {
                uint32_t h0 = (nt < 2 ? bh0[(nt & 1) * 2]     : bh1[(nt & 1) * 2]);
                uint32_t h1 = (nt < 2 ? bh0[(nt & 1) * 2 + 1] : bh1[(nt & 1) * 2 + 1]);
                uint32_t l0 = (nt < 2 ? bl0[(nt & 1) * 2]     : bl1[(nt & 1) * 2]);
                uint32_t l1 = (nt < 2 ? bl0[(nt & 1) * 2 + 1] : bl1[(nt & 1) * 2 + 1]);
                mma_bf16(acc[0][nt], ah0, h0, h1);
                mma_bf16(acc[1][nt], ah1, h0, h1);
                mma_bf16(acc[0][nt], ah0, l0, l1);
                mma_bf16(acc[1][nt], ah1, l0, l1);
                mma_bf16(acc[0][nt], al0, h0, h1);
                mma_bf16(acc[1][nt], al1, h0, h1);
            }
        }
        __syncthreads();
    }

    const int g = lane >> 2, t = lane & 3;
#pragma unroll
    for (int mt = 0; mt < 2; mt++) {
        int r0 = m0 + wm * 32 + mt * 16 + g;
        int r1 = r0 + 8;
        int o0 = r0, o1 = r1;
        if (EPI == EPI_PROJ) { o0 = proj_remap(r0); o1 = proj_remap(r1); }
#pragma unroll
        for (int nt = 0; nt < 4; nt++) {
            int col = n0 + wn * 32 + nt * 8 + 2 * t;
            float b0 = bias[col], b1 = bias[col + 1];
            float v0 = acc[mt][nt][0] + b0, v1 = acc[mt][nt][1] + b1;
            float v2 = acc[mt][nt][2] + b0, v3 = acc[mt][nt][3] + b1;
            if (EPI == EPI_QKV) {
                *(float2*)&outf[(size_t)r0 * NTOT + col] = make_float2(v0, v1);
                *(float2*)&outf[(size_t)r1 * NTOT + col] = make_float2(v2, v3);
            } else if (EPI == EPI_PROJ) {
                const float2 s0 = *(const float2*)&res[(size_t)o0 * NTOT + col];
                const float2 s1 = *(const float2*)&res[(size_t)o1 * NTOT + col];
                *(float2*)&outf[(size_t)o0 * NTOT + col] = make_float2(s0.x + v0, s0.y + v1);
                *(float2*)&outf[(size_t)o1 * NTOT + col] = make_float2(s1.x + v2, s1.y + v3);
            } else if (EPI == EPI_GELU) {
                float g0 = 0.5f * v0 * (1.f + erff(v0 * 0.7071067811865475f));
                float g1 = 0.5f * v1 * (1.f + erff(v1 * 0.7071067811865475f));
                float g2 = 0.5f * v2 * (1.f + erff(v2 * 0.7071067811865475f));
                float g3 = 0.5f * v3 * (1.f + erff(v3 * 0.7071067811865475f));
                __nv_bfloat16 h0 = __float2bfloat16(g0), h1 = __float2bfloat16(g1);
                __nv_bfloat16 h2 = __float2bfloat16(g2), h3 = __float2bfloat16(g3);
                *(__nv_bfloat162*)&outh[(size_t)r0 * NTOT + col] = __nv_bfloat162(h0, h1);
                *(__nv_bfloat162*)&outh[(size_t)r1 * NTOT + col] = __nv_bfloat162(h2, h3);
                *(__nv_bfloat162*)&outl[(size_t)r0 * NTOT + col] = __nv_bfloat162(
                    __float2bfloat16(g0 - __bfloat162float(h0)), __float2bfloat16(g1 - __bfloat162float(h1)));
                *(__nv_bfloat162*)&outl[(size_t)r1 * NTOT + col] = __nv_bfloat162(
                    __float2bfloat16(g2 - __bfloat162float(h2)), __float2bfloat16(g3 - __bfloat162float(h3)));
            } else {
                const float2 s0 = *(const float2*)&res[(size_t)r0 * NTOT + col];
                const float2 s1 = *(const float2*)&res[(size_t)r1 * NTOT + col];
                *(float2*)&outf[(size_t)r0 * NTOT + col] = make_float2(s0.x + v0, s0.y + v1);
                *(float2*)&outf[(size_t)r1 * NTOT + col] = make_float2(s1.x + v2, s1.y + v3);
            }
        }
    }
}

// ---------------- attention v6: R11 register-P + compact smem (8 CTAs/SM) ----------------
// Q/K buffers hold only 49 real rows (stride 3920B); ldmatrix reads past row 48
// land in the next buffer: Q garbage rows -> outputs discarded (r<49 guard);
// K garbage rows -> score cols >=49, which softmax guards zero exactly before P.
// V cols 49..63 MUST be real zeros (P=0 x NaN would poison AV) -> keep pad loop.
#define QKP 40
#define VTP 72
#define AQH 0u
#define AQL 3920u
#define AKH 7840u
#define AKL 11760u
#define AVH 15680u
#define AVL 20288u
#define ATTN_SMEM 24896

__global__ void __launch_bounds__(128) attn_mma()
{
    extern __shared__ __align__(16) char SM[];
    __nv_bfloat16* sQh = (__nv_bfloat16*)(SM + AQH);
    __nv_bfloat16* sQl = (__nv_bfloat16*)(SM + AQL);
    __nv_bfloat16* sKh = (__nv_bfloat16*)(SM + AKH);
    __nv_bfloat16* sKl = (__nv_bfloat16*)(SM + AKL);
    __nv_bfloat16* sVh = (__nv_bfloat16*)(SM + AVH);
    __nv_bfloat16* sVl = (__nv_bfloat16*)(SM + AVL);

    const int win = blockIdx.x / NHEAD;
    const int h   = blockIdx.x % NHEAD;
    const int tid = threadIdx.x;
    const int lane = tid & 31, w = tid >> 5;

    // ---- zero pad: VT cols 49..63 only (P is exactly 0 there, but 0*NaN = NaN) ----
    for (int i = tid; i < 32 * 15; i += 128) {
        int d = i / 15, j = 49 + i % 15;
        sVh[d * VTP + j] = __nv_bfloat16(0.f);
        sVl[d * VTP + j] = __nv_bfloat16(0.f);
    }

    // ---- load + split q (pre-scaled), k, v ----
    const float scale = 0.17677669529663687f;  // 32^-0.5, folded into Q
    const float* base = g_qkv + (size_t)win * 49 * (3 * CH) + h * 32;
    for (int i = tid; i < 49 * 32; i += 128) {
        int t = i >> 5, d = i & 31;
        const float* p = base + (size_t)t * (3 * CH) + d;
        float qv = p[0] * scale, kv = p[CH], vv = p[2 * CH];
        split_store(qv, &sQh[t * QKP + d], &sQl[t * QKP + d]);
        split_store(kv, &sKh[t * QKP + d], &sKl[t * QKP + d]);
        split_store(vv, &sVh[d * VTP + t], &sVl[d * VTP + t]);
    }
    __syncthreads();   // the ONLY block-wide sync

    const uint32_t sb = smem_u32(SM);
    const int g = lane >> 2, t4 = lane & 3;
    const int r0 = w * 16 + g, r1 = r0 + 8;

    // ---- QK^T: warp w -> score rows r0,r1 over cols 0..63, in registers ----
    float acc[8][4];
#pragma unroll
    for (int i = 0; i < 8; i++)
#pragma unroll
        for (int j = 0; j < 4; j++) acc[i][j] = 0.f;

    {
        const uint32_t aoff = (uint32_t)((w * 16 + (lane & 15)) * QKP + (lane >> 4) * 8) * 2;
        const uint32_t adrQh = sb + AQH + aoff;
        const uint32_t adrQl = sb + AQL + aoff;
        const uint32_t brow  = (uint32_t)((lane & 7) + ((lane >> 4) << 3));
        const uint32_t bcol  = (uint32_t)(((lane >> 3) & 1) * 8);

#pragma unroll
        for (int ks = 0; ks < 2; ks++) {
            const uint32_t kb = (uint32_t)(ks * 32);
            uint32_t qh[4], ql[4];
            ldm_x4(qh, adrQh + kb);
            ldm_x4(ql, adrQl + kb);
#pragma unroll
            for (int nb = 0; nb < 4; nb++) {
                const uint32_t boff = (uint32_t)((nb * 16 + brow) * QKP + bcol) * 2 + kb;
                uint32_t kh[4], kl[4];
                ldm_x4(kh, sb + AKH + boff);
                ldm_x4(kl, sb + AKL + boff);
#pragma unroll
                for (int s = 0; s < 2; s++) {
                    int nt = nb * 2 + s;
                    mma_bf16(acc[nt], qh, kh[s * 2], kh[s * 2 + 1]);
                    mma_bf16(acc[nt], qh, kl[s * 2], kl[s * 2 + 1]);
                    mma_bf16(acc[nt], ql, kh[s * 2], kh[s * 2 + 1]);
                }
            }
        }
    }

    // ---- register softmax over rows r0 (acc[][0..1]) and r1 (acc[][2..3]) ----
    {
        float mx0 = -1e30f, mx1 = -1e30f;
#pragma unroll
        for (int nt = 0; nt < 8; nt++) {
            int col = nt * 8 + 2 * t4;
            if (col < 49)     { mx0 = fmaxf(mx0, acc[nt][0]); mx1 = fmaxf(mx1, acc[nt][2]); }
            if (col + 1 < 49) { mx0 = fmaxf(mx0, acc[nt][1]); mx1 = fmaxf(mx1, acc[nt][3]); }
        }
        mx0 = fmaxf(mx0, __shfl_xor_sync(0xffffffffu, mx0, 1));
        mx0 = fmaxf(mx0, __shfl_xor_sync(0xffffffffu, mx0, 2));
        mx1 = fmaxf(mx1, __shfl_xor_sync(0xffffffffu, mx1, 1));
        mx1 = fmaxf(mx1, __shfl_xor_sync(0xffffffffu, mx1, 2));

        float s0 = 0.f, s1 = 0.f;
#pragma unroll
        for (int nt = 0; nt < 8; nt++) {
            int col = nt * 8 + 2 * t4;
            float e0 = (col < 49)     ? expf(acc[nt][0] - mx0) : 0.f;
            float e1 = (col + 1 < 49) ? expf(acc[nt][1] - mx0) : 0.f;
            float e2 = (col < 49)     ? expf(acc[nt][2] - mx1) : 0.f;
            float e3 = (col + 1 < 49) ? expf(acc[nt][3] - mx1) : 0.f;
            acc[nt][0] = e0; acc[nt][1] = e1; acc[nt][2] = e2; acc[nt][3] = e3;
            s0 += e0 + e1; s1 += e2 + e3;
        }
        s0 += __shfl_xor_sync(0xffffffffu, s0, 1);
        s0 += __shfl_xor_sync(0xffffffffu, s0, 2);
        s1 += __shfl_xor_sync(0xffffffffu, s1, 1);
        s1 += __shfl_xor_sync(0xffffffffu, s1, 2);
        float inv0 = 1.f / s0, inv1 = 1.f / s1;

#pragma unroll
        for (int nt = 0; nt < 8; nt++) {
            acc[nt][0] *= inv0; acc[nt][1] *= inv0;
            acc[nt][2] *= inv1; acc[nt][3] *= inv1;
        }
    }

    // ---- AV: P consumed directly from registers ----
    {
        const uint32_t brow = (uint32_t)((lane & 7) + ((lane >> 4) << 3));
        const uint32_t bcol = (uint32_t)(((lane >> 3) & 1) * 8);

        float oacc[4][4];
#pragma unroll
        for (int i = 0; i < 4; i++)
#pragma unroll
            for (int j = 0; j < 4; j++) oacc[i][j] = 0.f;

#pragma unroll
        for (int ks = 0; ks < 4; ks++) {
            uint32_t ph[4], pl[4];
            ph[0] = pack_bf16(acc[2 * ks][0],     acc[2 * ks][1]);
            ph[1] = pack_bf16(acc[2 * ks][2],     acc[2 * ks][3]);
            ph[2] = pack_bf16(acc[2 * ks + 1][0], acc[2 * ks + 1][1]);
            ph[3] = pack_bf16(acc[2 * ks + 1][2], acc[2 * ks + 1][3]);
            pl[0] = pack_bf16_lo(acc[2 * ks][0],     acc[2 * ks][1],     ph[0]);
            pl[1] = pack_bf16_lo(acc[2 * ks][2],     acc[2 * ks][3],     ph[1]);
            pl[2] = pack_bf16_lo(acc[2 * ks + 1][0], acc[2 * ks + 1][1], ph[2]);
            pl[3] = pack_bf16_lo(acc[2 * ks + 1][2], acc[2 * ks + 1][3], ph[3]);

            const uint32_t kb = (uint32_t)(ks * 32);
#pragma unroll
            for (int nb = 0; nb < 2; nb++) {
                const uint32_t boff = (uint32_t)((nb * 16 + brow) * VTP + bcol) * 2 + kb;
                uint32_t vh[4], vl[4];
                ldm_x4(vh, sb + AVH + boff);
                ldm_x4(vl, sb + AVL + boff);
#pragma unroll
                for (int s = 0; s < 2; s++) {
                    int nt = nb * 2 + s;
                    mma_bf16(oacc[nt], ph, vh[s * 2], vh[s * 2 + 1]);
                    mma_bf16(oacc[nt], ph, vl[s * 2], vl[s * 2 + 1]);
                    mma_bf16(oacc[nt], pl, vh[s * 2], vh[s * 2 + 1]);
                }
            }
        }

        const size_t ob = (size_t)win * 49 * CH + h * 32;
#pragma unroll
        for (int nt = 0; nt < 4; nt++) {
            int d = nt * 8 + t4 * 2;
            if (r0 < 49) {
                float v0 = oacc[nt][0], v1 = oacc[nt][1];
                __nv_bfloat16 h0 = __float2bfloat16(v0), h1 = __float2bfloat16(v1);
                *(__nv_bfloat162*)&g_ob_h[ob + (size_t)r0 * CH + d] = __nv_bfloat162(h0, h1);
                *(__nv_bfloat162*)&g_ob_l[ob + (size_t)r0 * CH + d] = __nv_bfloat162(
                    __float2bfloat16(v0 - __bfloat162float(h0)), __float2bfloat16(v1 - __bfloat162float(h1)));
            }
            if (r1 < 49) {
                float v2 = oacc[nt][2], v3 = oacc[nt][3];
                __nv_bfloat16 h2 = __float2bfloat16(v2), h3 = __float2bfloat16(v3);
                *(__nv_bfloat162*)&g_ob_h[ob + (size_t)r1 * CH + d] = __nv_bfloat162(h2, h3);
                *(__nv_bfloat162*)&g_ob_l[ob + (size_t)r1 * CH + d] = __nv_bfloat162(
                    __float2bfloat16(v2 - __bfloat162float(h2)), __float2bfloat16(v3 - __bfloat162float(h3)));
            }
        }
    }
}

// ---------------- launch ----------------
extern "C" void kernel_launch(void* const* d_in, const int* in_sizes, int n_in,
                              void* d_out, int out_size)
{
    const float* x      = (const float*)d_in[0];
    const float* ln1_w  = (const float*)d_in[1];
    const float* ln1_b  = (const float*)d_in[2];
    const float* qkv_w  = (const float*)d_in[3];
    const float* qkv_b  = (const float*)d_in[4];
    const float* proj_w = (const float*)d_in[5];
    const float* proj_b = (const float*)d_in[6];
    const float* ln2_w  = (const float*)d_in[7];
    const float* ln2_b  = (const float*)d_in[8];
    const float* mlp_w1 = (const float*)d_in[9];
    const float* mlp_b1 = (const float*)d_in[10];
    const float* mlp_w2 = (const float*)d_in[11];
    const float* mlp_b2 = (const float*)d_in[12];
    float* out = (float*)d_out;

    float *p_qkv, *p_x1;
    __nv_bfloat16 *p_xw_h, *p_xw_l, *p_ob_h, *p_ob_l, *p_hin_h, *p_hin_l, *p_h_h, *p_h_l;
    __nv_bfloat16 *p_wqkv_h, *p_wqkv_l, *p_wprj_h, *p_wprj_l, *p_wm1_h, *p_wm1_l, *p_wm2_h, *p_wm2_l;
    cudaGetSymbolAddress((void**)&p_qkv,    g_qkv);
    cudaGetSymbolAddress((void**)&p_x1,     g_x1);
    cudaGetSymbolAddress((void**)&p_xw_h,   g_xw_h);
    cudaGetSymbolAddress((void**)&p_xw_l,   g_xw_l);
    cudaGetSymbolAddress((void**)&p_ob_h,   g_ob_h);
    cudaGetSymbolAddress((void**)&p_ob_l,   g_ob_l);
    cudaGetSymbolAddress((void**)&p_hin_h,  g_hin_h);
    cudaGetSymbolAddress((void**)&p_hin_l,  g_hin_l);
    cudaGetSymbolAddress((void**)&p_h_h,    g_h_h);
    cudaGetSymbolAddress((void**)&p_h_l,    g_h_l);
    cudaGetSymbolAddress((void**)&p_wqkv_h, g_wqkv_h);
    cudaGetSymbolAddress((void**)&p_wqkv_l, g_wqkv_l);
    cudaGetSymbolAddress((void**)&p_wprj_h, g_wprj_h);
    cudaGetSymbolAddress((void**)&p_wprj_l, g_wprj_l);
    cudaGetSymbolAddress((void**)&p_wm1_h,  g_wm1_h);
    cudaGetSymbolAddress((void**)&p_wm1_l,  g_wm1_l);
    cudaGetSymbolAddress((void**)&p_wm2_h,  g_wm2_h);
    cudaGetSymbolAddress((void**)&p_wm2_l,  g_wm2_l);

    cudaFuncSetAttribute(tgemm<EPI_QKV, 576, 192>,  cudaFuncAttributeMaxDynamicSharedMemorySize, SMEM_DYN);
    cudaFuncSetAttribute(tgemm<EPI_PROJ, 192, 192>, cudaFuncAttributeMaxDynamicSharedMemorySize, SMEM_DYN);
    cudaFuncSetAttribute(tgemm<EPI_GELU, 768, 192>, cudaFuncAttributeMaxDynamicSharedMemorySize, SMEM_DYN);
    cudaFuncSetAttribute(tgemm<EPI_ADD, 192, 768>,  cudaFuncAttributeMaxDynamicSharedMemorySize, SMEM_DYN);
    cudaFuncSetAttribute(attn_mma, cudaFuncAttributeMaxDynamicSharedMemorySize, ATTN_SMEM);

    wprep_all<<<(WTOT_E + 255) / 256, 256>>>(qkv_w, proj_w, mlp_w1, mlp_w2,
                                             p_wqkv_h, p_wqkv_l, p_wprj_h, p_wprj_l,
                                             p_wm1_h, p_wm1_l, p_wm2_h, p_wm2_l);

    const int LN_BLOCKS = TOK / 8;

    ln_kernel<true><<<LN_BLOCKS, 256>>>(x, ln1_w, ln1_b, p_xw_h, p_xw_l);

    tgemm<EPI_QKV, 576, 192><<<dim3(9, TOK / 128), 256, SMEM_DYN>>>(
        p_xw_h, p_xw_l, p_wqkv_h, p_wqkv_l, qkv_b, p_qkv, nullptr, nullptr, nullptr);

    attn_mma<<<NWIN * NHEAD, 128, ATTN_SMEM>>>();

    tgemm<EPI_PROJ, 192, 192><<<dim3(3, TOK / 128), 256, SMEM_DYN>>>(
        p_ob_h, p_ob_l, p_wprj_h, p_wprj_l, proj_b, p_x1, nullptr, nullptr, x);

    ln_kernel<false><<<LN_BLOCKS, 256>>>(p_x1, ln2_w, ln2_b, p_hin_h, p_hin_l);

    tgemm<EPI_GELU, 768, 192><<<dim3(12, TOK / 128), 256, SMEM_DYN>>>(
        p_hin_h, p_hin_l, p_wm1_h, p_wm1_l, mlp_b1, nullptr, p_h_h, p_h_l, nullptr);

    tgemm<EPI_ADD, 192, 768><<<dim3(3, TOK / 128), 256, SMEM_DYN>>>(
        p_h_h, p_h_l, p_wm2_h, p_wm2_l, mlp_b2, out, nullptr, nullptr, p_x1);
}

// round 16
// speedup vs baseline: 1.3239x; 1.2679x over previous
#include <cuda_runtime.h>
#include <cuda_bf16.h>
#include <cuda_fp16.h>
#include <math.h>
#include <stdint.h>

// ---------------- problem constants ----------------
#define HH    56
#define WW    56
#define CH    192
#define TOK   50176        // 16*56*56
#define NHEAD 6
#define HID   768
#define NWIN  1024
#define WSZ   7
#define SHF   3

// ---------------- scratch (device globals, no allocs) ----------------
__device__ __half  g_xw_h [TOK * CH];
__device__ __half  g_xw_l [TOK * CH];
__device__ float   g_qkv  [TOK * 3 * CH];
__device__ __half  g_ob_h [TOK * CH];
__device__ __half  g_ob_l [TOK * CH];
__device__ float   g_x1   [TOK * CH];
__device__ __half  g_hin_h[TOK * CH];
__device__ __half  g_hin_l[TOK * CH];
__device__ __half  g_h_h  [TOK * HID];
__device__ __half  g_h_l  [TOK * HID];
// transposed weights, [N, K] row-major, single fp16
__device__ __half  g_wqkv [3 * CH * CH];
__device__ __half  g_wprj [CH * CH];
__device__ __half  g_wm1  [HID * CH];
__device__ __half  g_wm2  [CH * HID];

// ---------------- helpers ----------------
__device__ __forceinline__ uint32_t smem_u32(const void* p) {
    uint32_t a;
    asm("{ .reg .u64 t; cvta.to.shared.u64 t, %1; cvt.u32.u64 %0, t; }" : "=r"(a) : "l"(p));
    return a;
}

__device__ __forceinline__ void ldm_x4(uint32_t* r, uint32_t addr) {
    asm volatile("ldmatrix.sync.aligned.m8n8.x4.shared.b16 {%0,%1,%2,%3}, [%4];"
                 : "=r"(r[0]), "=r"(r[1]), "=r"(r[2]), "=r"(r[3]) : "r"(addr));
}

__device__ __forceinline__ void mma_bf16(float* d, const uint32_t* a, uint32_t b0, uint32_t b1) {
    asm volatile("mma.sync.aligned.m16n8k16.row.col.f32.bf16.bf16.f32 "
                 "{%0,%1,%2,%3}, {%4,%5,%6,%7}, {%8,%9}, {%0,%1,%2,%3};"
                 : "+f"(d[0]), "+f"(d[1]), "+f"(d[2]), "+f"(d[3])
                 : "r"(a[0]), "r"(a[1]), "r"(a[2]), "r"(a[3]), "r"(b0), "r"(b1));
}

__device__ __forceinline__ void mma_f16(float* d, const uint32_t* a, uint32_t b0, uint32_t b1) {
    asm volatile("mma.sync.aligned.m16n8k16.row.col.f32.f16.f16.f32 "
                 "{%0,%1,%2,%3}, {%4,%5,%6,%7}, {%8,%9}, {%0,%1,%2,%3};"
                 : "+f"(d[0]), "+f"(d[1]), "+f"(d[2]), "+f"(d[3])
                 : "r"(a[0]), "r"(a[1]), "r"(a[2]), "r"(a[3]), "r"(b0), "r"(b1));
}

__device__ __forceinline__ void cp16(uint32_t dst, const void* src) {
    asm volatile("cp.async.cg.shared.global [%0], [%1], 16;" :: "r"(dst), "l"(src));
}

// bf16 split helpers (attention internals)
__device__ __forceinline__ void split_store_b(float v, __nv_bfloat16* ph, __nv_bfloat16* pl) {
    __nv_bfloat16 h = __float2bfloat16(v);
    *ph = h;
    *pl = __float2bfloat16(v - __bfloat162float(h));
}
__device__ __forceinline__ uint32_t pack_bf16(float a, float b) {
    __nv_bfloat162 t(__float2bfloat16(a), __float2bfloat16(b));
    return *reinterpret_cast<uint32_t*>(&t);
}
__device__ __forceinline__ uint32_t pack_bf16_lo(float a, float b, uint32_t hi) {
    __nv_bfloat162 h = *reinterpret_cast<__nv_bfloat162*>(&hi);
    __nv_bfloat162 t(__float2bfloat16(a - __bfloat162float(h.x)),
                     __float2bfloat16(b - __bfloat162float(h.y)));
    return *reinterpret_cast<uint32_t*>(&t);
}

// fp16 split helpers (GEMM operands)
__device__ __forceinline__ void split_store_h(float v, __half* ph, __half* pl) {
    __half h = __float2half(v);
    *ph = h;
    *pl = __float2half(v - __half2float(h));
}
__device__ __forceinline__ void split_store2_h(float a, float b, __half* ph, __half* pl) {
    __half ha = __float2half(a), hb = __float2half(b);
    *(__half2*)ph = __half2(ha, hb);
    *(__half2*)pl = __half2(__float2half(a - __half2float(ha)),
                            __float2half(b - __half2float(hb)));
}

__device__ __forceinline__ int proj_remap(int grow) {
    int win = grow / 49, tt = grow % 49;
    int bb  = win >> 6, rem = win & 63;
    int ii  = (rem >> 3) * WSZ + tt / WSZ;
    int jj  = (rem & 7)  * WSZ + tt % WSZ;
    int yi  = ii + SHF; if (yi >= HH) yi -= HH;
    int xj  = jj + SHF; if (xj >= WW) xj -= WW;
    return (bb * HH + yi) * WW + xj;
}

// ---------------- fused weight prep: transpose [K,N] -> fp16 [N,K] ----------------
#define WQKV_E (CH * 3 * CH)
#define WPRJ_E (CH * CH)
#define WM1_E  (CH * HID)
#define WM2_E  (HID * CH)
#define WTOT_E (WQKV_E + WPRJ_E + WM1_E + WM2_E)

__global__ void __launch_bounds__(256) wprep_all(
    const float* __restrict__ qkvw, const float* __restrict__ prjw,
    const float* __restrict__ m1w,  const float* __restrict__ m2w,
    __half* __restrict__ wq, __half* __restrict__ wp,
    __half* __restrict__ w1, __half* __restrict__ w2)
{
    int i = blockIdx.x * 256 + threadIdx.x;
    if (i >= WTOT_E) return;
    const float* src; __half* dst; int K, N;
    if (i < WQKV_E)                       { src = qkvw; dst = wq; K = CH;  N = 3 * CH; }
    else if (i < WQKV_E + WPRJ_E)         { i -= WQKV_E;          src = prjw; dst = wp; K = CH;  N = CH; }
    else if (i < WQKV_E + WPRJ_E + WM1_E) { i -= WQKV_E + WPRJ_E; src = m1w;  dst = w1; K = CH;  N = HID; }
    else                                  { i -= WQKV_E + WPRJ_E + WM1_E; src = m2w; dst = w2; K = HID; N = CH; }
    int n = i / K, k = i - n * K;
    dst[i] = __float2half(src[(size_t)k * N + n]);
}

// ---------------- LN (warp per row) writing fp16 hi/lo ----------------
template<bool GATHER>
__global__ void __launch_bounds__(256) ln_kernel(const float* __restrict__ x,
                                                 const float* __restrict__ w,
                                                 const float* __restrict__ b,
                                                 __half* __restrict__ oh,
                                                 __half* __restrict__ ol)
{
    int row  = (blockIdx.x * blockDim.x + threadIdx.x) >> 5;
    int lane = threadIdx.x & 31;
    if (row >= TOK) return;

    int src_row;
    if (GATHER) {
        int win = row / 49, t = row % 49;
        int bb  = win >> 6, rem = win & 63;
        int i   = (rem >> 3) * WSZ + t / WSZ;
        int j   = (rem & 7)  * WSZ + t % WSZ;
        int yi  = i + SHF; if (yi >= HH) yi -= HH;
        int xj  = j + SHF; if (xj >= WW) xj -= WW;
        src_row = (bb * HH + yi) * WW + xj;
    } else src_row = row;

    const float* px = x + (size_t)src_row * CH;
    float v[6];
    float s = 0.f, s2 = 0.f;
#pragma unroll
    for (int u = 0; u < 6; u++) { v[u] = px[lane + 32 * u]; s += v[u]; s2 += v[u] * v[u]; }
#pragma unroll
    for (int o = 16; o; o >>= 1) {
        s  += __shfl_xor_sync(0xffffffffu, s,  o);
        s2 += __shfl_xor_sync(0xffffffffu, s2, o);
    }
    float mean = s * (1.f / CH);
    float var  = s2 * (1.f / CH) - mean * mean;
    float rstd = rsqrtf(var + 1e-5f);
#pragma unroll
    for (int u = 0; u < 6; u++) {
        int c = lane + 32 * u;
        float val = (v[u] - mean) * rstd * w[c] + b[c];
        split_store_h(val, oh + (size_t)row * CH + c, ol + (size_t)row * CH + c);
    }
}

// ---------------- mma.sync fp16 A-split GEMM: tile M=128 x N=64, K-chunk 64, 2 MMAs ----------------
enum { EPI_QKV = 0, EPI_PROJ = 1, EPI_GELU = 2, EPI_ADD = 3 };

#define KP   72
#define STG_AH 0u
#define STG_AL 18432u
#define STG_BH 36864u
#define STG_BYTES 46080u
#define SMEM_DYN (2 * 46080)

template<int EPI, int NTOT, int KTOT>
__global__ void __launch_bounds__(256) tgemm(
    const __half* __restrict__ Ah, const __half* __restrict__ Al,
    const __half* __restrict__ Bh,
    const float* __restrict__ bias,
    float* __restrict__ outf,
    __half* __restrict__ outh, __half* __restrict__ outl,
    const float* __restrict__ res)
{
    extern __shared__ __half S[];
    const uint32_t sbase = smem_u32(S);

    const int tid  = threadIdx.x;
    const int lane = tid & 31, wid = tid >> 5;
    const int wm   = wid & 3,  wn  = wid >> 2;
    const int n0   = blockIdx.x * 64;
    const int m0   = blockIdx.y * 128;

    const uint32_t aOff = (uint32_t)((wm * 32 + (lane & 15)) * KP + (lane >> 4) * 8) * 2;
    const uint32_t bOff = (uint32_t)((wn * 32 + (lane & 7) + ((lane >> 4) << 3)) * KP + ((lane >> 3) & 1) * 8) * 2;

    float acc[2][4][4];
#pragma unroll
    for (int i = 0; i < 2; i++)
#pragma unroll
        for (int j = 0; j < 4; j++)
#pragma unroll
            for (int q = 0; q < 4; q++) acc[i][j][q] = 0.f;

    const int KCH = KTOT / 64;

    auto issue = [&](int kc) {
        const uint32_t so = sbase + (uint32_t)(kc & 1) * STG_BYTES;
        const size_t abase = (size_t)m0 * KTOT + (size_t)kc * 64;
        const size_t bbase = (size_t)n0 * KTOT + (size_t)kc * 64;
#pragma unroll
        for (int i = tid; i < 128 * 8; i += 256) {
            int r = i >> 3, c = i & 7;
            uint32_t d = so + (uint32_t)(r * KP + c * 8) * 2;
            const size_t g = abase + (size_t)r * KTOT + c * 8;
            cp16(d + STG_AH, Ah + g);
            cp16(d + STG_AL, Al + g);
        }
#pragma unroll
        for (int i = tid; i < 64 * 8; i += 256) {
            int r = i >> 3, c = i & 7;
            uint32_t d = so + (uint32_t)(r * KP + c * 8) * 2;
            cp16(d + STG_BH, Bh + bbase + (size_t)r * KTOT + c * 8);
        }
        asm volatile("cp.async.commit_group;" ::: "memory");
    };

    issue(0);

    for (int kc = 0; kc < KCH; kc++) {
        if (kc + 1 < KCH) {
            issue(kc + 1);
            asm volatile("cp.async.wait_group 1;" ::: "memory");
        } else {
            asm volatile("cp.async.wait_group 0;" ::: "memory");
        }
        __syncthreads();

        const uint32_t so = sbase + (uint32_t)(kc & 1) * STG_BYTES;
        const uint32_t adrAh0 = so + STG_AH + aOff, adrAh1 = adrAh0 + 16 * KP * 2;
        const uint32_t adrAl0 = so + STG_AL + aOff, adrAl1 = adrAl0 + 16 * KP * 2;
        const uint32_t adrBh0 = so + STG_BH + bOff, adrBh1 = adrBh0 + 16 * KP * 2;

#pragma unroll
        for (int ks = 0; ks < 4; ks++) {
            const uint32_t kb = (uint32_t)(ks * 32);
            uint32_t ah0[4], ah1[4], al0[4], al1[4];
            uint32_t bh0[4], bh1[4];
            ldm_x4(ah0, adrAh0 + kb);
            ldm_x4(ah1, adrAh1 + kb);
            ldm_x4(al0, adrAl0 + kb);
            ldm_x4(al1, adrAl1 + kb);
            ldm_x4(bh0, adrBh0 + kb);
            ldm_x4(bh1, adrBh1 + kb);

#pragma unroll
            for (int nt = 0; nt < 4; nt++) {
                uint32_t h0 = (nt < 2 ? bh0[(nt & 1) * 2]     : bh1[(nt & 1) * 2]);
                uint32_t h1 = (nt < 2 ? bh0[(nt & 1) * 2 + 1] : bh1[(nt & 1) * 2 + 1]);
                mma_f16(acc[0][nt], ah0, h0, h1);
                mma_f16(acc[1][nt], ah1, h0, h1);
                mma_f16(acc[0][nt], al0, h0, h1);
                mma_f16(acc[1][nt], al1, h0, h1);
            }
        }
        __syncthreads();
    }

    const int g = lane >> 2, t = lane & 3;
#pragma unroll
    for (int mt = 0; mt < 2; mt++) {
        int r0 = m0 + wm * 32 + mt * 16 + g;
        int r1 = r0 + 8;
        int o0 = r0, o1 = r1;
        if (EPI == EPI_PROJ) { o0 = proj_remap(r0); o1 = proj_remap(r1); }
#pragma unroll
        for (int nt = 0; nt < 4; nt++) {
            int col = n0 + wn * 32 + nt * 8 + 2 * t;
            float b0 = bias[col], b1 = bias[col + 1];
            float v0 = acc[mt][nt][0] + b0, v1 = acc[mt][nt][1] + b1;
            float v2 = acc[mt][nt][2] + b0, v3 = acc[mt][nt][3] + b1;
            if (EPI == EPI_QKV) {
                *(float2*)&outf[(size_t)r0 * NTOT + col] = make_float2(v0, v1);
                *(float2*)&outf[(size_t)r1 * NTOT + col] = make_float2(v2, v3);
            } else if (EPI == EPI_PROJ) {
                const float2 s0 = *(const float2*)&res[(size_t)o0 * NTOT + col];
                const float2 s1 = *(const float2*)&res[(size_t)o1 * NTOT + col];
                *(float2*)&outf[(size_t)o0 * NTOT + col] = make_float2(s0.x + v0, s0.y + v1);
                *(float2*)&outf[(size_t)o1 * NTOT + col] = make_float2(s1.x + v2, s1.y + v3);
            } else if (EPI == EPI_GELU) {
                float g0 = 0.5f * v0 * (1.f + erff(v0 * 0.7071067811865475f));
                float g1 = 0.5f * v1 * (1.f + erff(v1 * 0.7071067811865475f));
                float g2 = 0.5f * v2 * (1.f + erff(v2 * 0.7071067811865475f));
                float g3 = 0.5f * v3 * (1.f + erff(v3 * 0.7071067811865475f));
                split_store2_h(g0, g1, &outh[(size_t)r0 * NTOT + col], &outl[(size_t)r0 * NTOT + col]);
                split_store2_h(g2, g3, &outh[(size_t)r1 * NTOT + col], &outl[(size_t)r1 * NTOT + col]);
            } else { // EPI_ADD
                const float2 s0 = *(const float2*)&res[(size_t)r0 * NTOT + col];
                const float2 s1 = *(const float2*)&res[(size_t)r1 * NTOT + col];
                *(float2*)&outf[(size_t)r0 * NTOT + col] = make_float2(s0.x + v0, s0.y + v1);
                *(float2*)&outf[(size_t)r1 * NTOT + col] = make_float2(s1.x + v2, s1.y + v3);
            }
        }
    }
}

// ---------------- attention (R15 config; internals bf16-split; output fp16 hi/lo) ----------------
#define QKP 40
#define VTP 72
#define AQH 0u
#define AQL 3920u
#define AKH 7840u
#define AKL 11760u
#define AVH 15680u
#define AVL 20288u
#define ATTN_SMEM 24896

__global__ void __launch_bounds__(128) attn_mma()
{
    extern __shared__ __align__(16) char SM[];
    __nv_bfloat16* sQh = (__nv_bfloat16*)(SM + AQH);
    __nv_bfloat16* sQl = (__nv_bfloat16*)(SM + AQL);
    __nv_bfloat16* sKh = (__nv_bfloat16*)(SM + AKH);
    __nv_bfloat16* sKl = (__nv_bfloat16*)(SM + AKL);
    __nv_bfloat16* sVh = (__nv_bfloat16*)(SM + AVH);
    __nv_bfloat16* sVl = (__nv_bfloat16*)(SM + AVL);

    const int win = blockIdx.x / NHEAD;
    const int h   = blockIdx.x % NHEAD;
    const int tid = threadIdx.x;
    const int lane = tid & 31, w = tid >> 5;

    for (int i = tid; i < 32 * 15; i += 128) {
        int d = i / 15, j = 49 + i % 15;
        sVh[d * VTP + j] = __nv_bfloat16(0.f);
        sVl[d * VTP + j] = __nv_bfloat16(0.f);
    }

    const float scale = 0.17677669529663687f;
    const float* base = g_qkv + (size_t)win * 49 * (3 * CH) + h * 32;
    for (int i = tid; i < 49 * 32; i += 128) {
        int t = i >> 5, d = i & 31;
        const float* p = base + (size_t)t * (3 * CH) + d;
        float qv = p[0] * scale, kv = p[CH], vv = p[2 * CH];
        split_store_b(qv, &sQh[t * QKP + d], &sQl[t * QKP + d]);
        split_store_b(kv, &sKh[t * QKP + d], &sKl[t * QKP + d]);
        split_store_b(vv, &sVh[d * VTP + t], &sVl[d * VTP + t]);
    }
    __syncthreads();

    const uint32_t sb = smem_u32(SM);
    const int g = lane >> 2, t4 = lane & 3;
    const int r0 = w * 16 + g, r1 = r0 + 8;

    float acc[8][4];
#pragma unroll
    for (int i = 0; i < 8; i++)
#pragma unroll
        for (int j = 0; j < 4; j++) acc[i][j] = 0.f;

    {
        const uint32_t aoff = (uint32_t)((w * 16 + (lane & 15)) * QKP + (lane >> 4) * 8) * 2;
        const uint32_t adrQh = sb + AQH + aoff;
        const uint32_t adrQl = sb + AQL + aoff;
        const uint32_t brow  = (uint32_t)((lane & 7) + ((lane >> 4) << 3));
        const uint32_t bcol  = (uint32_t)(((lane >> 3) & 1) * 8);

#pragma unroll
        for (int ks = 0; ks < 2; ks++) {
            const uint32_t kb = (uint32_t)(ks * 32);
            uint32_t qh[4], ql[4];
            ldm_x4(qh, adrQh + kb);
            ldm_x4(ql, adrQl + kb);
#pragma unroll
            for (int nb = 0; nb < 4; nb++) {
                const uint32_t boff = (uint32_t)((nb * 16 + brow) * QKP + bcol) * 2 + kb;
                uint32_t kh[4], kl[4];
                ldm_x4(kh, sb + AKH + boff);
                ldm_x4(kl, sb + AKL + boff);
#pragma unroll
                for (int s = 0; s < 2; s++) {
                    int nt = nb * 2 + s;
                    mma_bf16(acc[nt], qh, kh[s * 2], kh[s * 2 + 1]);
                    mma_bf16(acc[nt], qh, kl[s * 2], kl[s * 2 + 1]);
                    mma_bf16(acc[nt], ql, kh[s * 2], kh[s * 2 + 1]);
                }
            }
        }
    }

    {
        float mx0 = -1e30f, mx1 = -1e30f;
#pragma unroll
        for (int nt = 0; nt < 8; nt++) {
            int col = nt * 8 + 2 * t4;
            if (col < 49)     { mx0 = fmaxf(mx0, acc[nt][0]); mx1 = fmaxf(mx1, acc[nt][2]); }
            if (col + 1 < 49) { mx0 = fmaxf(mx0, acc[nt][1]); mx1 = fmaxf(mx1, acc[nt][3]); }
        }
        mx0 = fmaxf(mx0, __shfl_xor_sync(0xffffffffu, mx0, 1));
        mx0 = fmaxf(mx0, __shfl_xor_sync(0xffffffffu, mx0, 2));
        mx1 = fmaxf(mx1, __shfl_xor_sync(0xffffffffu, mx1, 1));
        mx1 = fmaxf(mx1, __shfl_xor_sync(0xffffffffu, mx1, 2));

        float s0 = 0.f, s1 = 0.f;
#pragma unroll
        for (int nt = 0; nt < 8; nt++) {
            int col = nt * 8 + 2 * t4;
            float e0 = (col < 49)     ? expf(acc[nt][0] - mx0) : 0.f;
            float e1 = (col + 1 < 49) ? expf(acc[nt][1] - mx0) : 0.f;
            float e2 = (col < 49)     ? expf(acc[nt][2] - mx1) : 0.f;
            float e3 = (col + 1 < 49) ? expf(acc[nt][3] - mx1) : 0.f;
            acc[nt][0] = e0; acc[nt][1] = e1; acc[nt][2] = e2; acc[nt][3] = e3;
            s0 += e0 + e1; s1 += e2 + e3;
        }
        s0 += __shfl_xor_sync(0xffffffffu, s0, 1);
        s0 += __shfl_xor_sync(0xffffffffu, s0, 2);
        s1 += __shfl_xor_sync(0xffffffffu, s1, 1);
        s1 += __shfl_xor_sync(0xffffffffu, s1, 2);
        float inv0 = 1.f / s0, inv1 = 1.f / s1;

#pragma unroll
        for (int nt = 0; nt < 8; nt++) {
            acc[nt][0] *= inv0; acc[nt][1] *= inv0;
            acc[nt][2] *= inv1; acc[nt][3] *= inv1;
        }
    }

    {
        const uint32_t brow = (uint32_t)((lane & 7) + ((lane >> 4) << 3));
        const uint32_t bcol = (uint32_t)(((lane >> 3) & 1) * 8);

        float oacc[4][4];
#pragma unroll
        for (int i = 0; i < 4; i++)
#pragma unroll
            for (int j = 0; j < 4; j++) oacc[i][j] = 0.f;

#pragma unroll
        for (int ks = 0; ks < 4; ks++) {
            uint32_t ph[4], pl[4];
            ph[0] = pack_bf16(acc[2 * ks][0],     acc[2 * ks][1]);
            ph[1] = pack_bf16(acc[2 * ks][2],     acc[2 * ks][3]);
            ph[2] = pack_bf16(acc[2 * ks + 1][0], acc[2 * ks + 1][1]);
            ph[3] = pack_bf16(acc[2 * ks + 1][2], acc[2 * ks + 1][3]);
            pl[0] = pack_bf16_lo(acc[2 * ks][0],     acc[2 * ks][1],     ph[0]);
            pl[1] = pack_bf16_lo(acc[2 * ks][2],     acc[2 * ks][3],     ph[1]);
            pl[2] = pack_bf16_lo(acc[2 * ks + 1][0], acc[2 * ks + 1][1], ph[2]);
            pl[3] = pack_bf16_lo(acc[2 * ks + 1][2], acc[2 * ks + 1][3], ph[3]);

            const uint32_t kb = (uint32_t)(ks * 32);
#pragma unroll
            for (int nb = 0; nb < 2; nb++) {
                const uint32_t boff = (uint32_t)((nb * 16 + brow) * VTP + bcol) * 2 + kb;
                uint32_t vh[4], vl[4];
                ldm_x4(vh, sb + AVH + boff);
                ldm_x4(vl, sb + AVL + boff);
#pragma unroll
                for (int s = 0; s < 2; s++) {
                    int nt = nb * 2 + s;
                    mma_bf16(oacc[nt], ph, vh[s * 2], vh[s * 2 + 1]);
                    mma_bf16(oacc[nt], ph, vl[s * 2], vl[s * 2 + 1]);
                    mma_bf16(oacc[nt], pl, vh[s * 2], vh[s * 2 + 1]);
                }
            }
        }

        const size_t ob = (size_t)win * 49 * CH + h * 32;
#pragma unroll
        for (int nt = 0; nt < 4; nt++) {
            int d = nt * 8 + t4 * 2;
            if (r0 < 49)
                split_store2_h(oacc[nt][0], oacc[nt][1],
                               &g_ob_h[ob + (size_t)r0 * CH + d], &g_ob_l[ob + (size_t)r0 * CH + d]);
            if (r1 < 49)
                split_store2_h(oacc[nt][2], oacc[nt][3],
                               &g_ob_h[ob + (size_t)r1 * CH + d], &g_ob_l[ob + (size_t)r1 * CH + d]);
        }
    }
}

// ---------------- launch ----------------
extern "C" void kernel_launch(void* const* d_in, const int* in_sizes, int n_in,
                              void* d_out, int out_size)
{
    const float* x      = (const float*)d_in[0];
    const float* ln1_w  = (const float*)d_in[1];
    const float* ln1_b  = (const float*)d_in[2];
    const float* qkv_w  = (const float*)d_in[3];
    const float* qkv_b  = (const float*)d_in[4];
    const float* proj_w = (const float*)d_in[5];
    const float* proj_b = (const float*)d_in[6];
    const float* ln2_w  = (const float*)d_in[7];
    const float* ln2_b  = (const float*)d_in[8];
    const float* mlp_w1 = (const float*)d_in[9];
    const float* mlp_b1 = (const float*)d_in[10];
    const float* mlp_w2 = (const float*)d_in[11];
    const float* mlp_b2 = (const float*)d_in[12];
    float* out = (float*)d_out;

    float *p_qkv, *p_x1;
    __half *p_xw_h, *p_xw_l, *p_ob_h, *p_ob_l, *p_hin_h, *p_hin_l, *p_h_h, *p_h_l;
    __half *p_wqkv, *p_wprj, *p_wm1, *p_wm2;
    cudaGetSymbolAddress((void**)&p_qkv,   g_qkv);
    cudaGetSymbolAddress((void**)&p_x1,    g_x1);
    cudaGetSymbolAddress((void**)&p_xw_h,  g_xw_h);
    cudaGetSymbolAddress((void**)&p_xw_l,  g_xw_l);
    cudaGetSymbolAddress((void**)&p_ob_h,  g_ob_h);
    cudaGetSymbolAddress((void**)&p_ob_l,  g_ob_l);
    cudaGetSymbolAddress((void**)&p_hin_h, g_hin_h);
    cudaGetSymbolAddress((void**)&p_hin_l, g_hin_l);
    cudaGetSymbolAddress((void**)&p_h_h,   g_h_h);
    cudaGetSymbolAddress((void**)&p_h_l,   g_h_l);
    cudaGetSymbolAddress((void**)&p_wqkv,  g_wqkv);
    cudaGetSymbolAddress((void**)&p_wprj,  g_wprj);
    cudaGetSymbolAddress((void**)&p_wm1,   g_wm1);
    cudaGetSymbolAddress((void**)&p_wm2,   g_wm2);

    cudaFuncSetAttribute(tgemm<EPI_QKV, 576, 192>,  cudaFuncAttributeMaxDynamicSharedMemorySize, SMEM_DYN);
    cudaFuncSetAttribute(tgemm<EPI_PROJ, 192, 192>, cudaFuncAttributeMaxDynamicSharedMemorySize, SMEM_DYN);
    cudaFuncSetAttribute(tgemm<EPI_GELU, 768, 192>, cudaFuncAttributeMaxDynamicSharedMemorySize, SMEM_DYN);
    cudaFuncSetAttribute(tgemm<EPI_ADD, 192, 768>,  cudaFuncAttributeMaxDynamicSharedMemorySize, SMEM_DYN);
    cudaFuncSetAttribute(attn_mma, cudaFuncAttributeMaxDynamicSharedMemorySize, ATTN_SMEM);

    wprep_all<<<(WTOT_E + 255) / 256, 256>>>(qkv_w, proj_w, mlp_w1, mlp_w2,
                                             p_wqkv, p_wprj, p_wm1, p_wm2);

    const int LN_BLOCKS = TOK / 8;

    // 1. LN1 + shift + window partition
    ln_kernel<true><<<LN_BLOCKS, 256>>>(x, ln1_w, ln1_b, p_xw_h, p_xw_l);

    // 2. qkv GEMM [50176 x 576], K=192
    tgemm<EPI_QKV, 576, 192><<<dim3(9, TOK / 128), 256, SMEM_DYN>>>(
        p_xw_h, p_xw_l, p_wqkv, qkv_b, p_qkv, nullptr, nullptr, nullptr);

    // 3. windowed attention
    attn_mma<<<NWIN * NHEAD, 128, ATTN_SMEM>>>();

    // 4. proj GEMM + window reverse + unshift + shortcut
    tgemm<EPI_PROJ, 192, 192><<<dim3(3, TOK / 128), 256, SMEM_DYN>>>(
        p_ob_h, p_ob_l, p_wprj, proj_b, p_x1, nullptr, nullptr, x);

    // 5. LN2
    ln_kernel<false><<<LN_BLOCKS, 256>>>(p_x1, ln2_w, ln2_b, p_hin_h, p_hin_l);

    // 6. mlp1 + GELU
    tgemm<EPI_GELU, 768, 192><<<dim3(12, TOK / 128), 256, SMEM_DYN>>>(
        p_hin_h, p_hin_l, p_wm1, mlp_b1, nullptr, p_h_h, p_h_l, nullptr);

    // 7. mlp2 + residual
    tgemm<EPI_ADD, 192, 768><<<dim3(3, TOK / 128), 256, SMEM_DYN>>>(
        p_h_h, p_h_l, p_wm2, mlp_b2, out, nullptr, nullptr, p_x1);
}

// round 17
// speedup vs baseline: 1.8915x; 1.4287x over previous
#include <cuda_runtime.h>
#include <cuda_bf16.h>
#include <cuda_fp16.h>
#include <math.h>
#include <stdint.h>

// ---------------- problem constants ----------------
#define HH    56
#define WW    56
#define CH    192
#define TOK   50176        // 16*56*56
#define NHEAD 6
#define HID   768
#define NWIN  1024
#define WSZ   7
#define SHF   3

// ---------------- scratch (device globals, no allocs) ----------------
__device__ __half  g_xw  [TOK * CH];
__device__ float   g_qkv [TOK * 3 * CH];
__device__ __half  g_ob  [TOK * CH];
__device__ float   g_x1  [TOK * CH];
__device__ __half  g_hin [TOK * CH];
__device__ __half  g_h   [TOK * HID];
// transposed weights, [N, K] row-major, single fp16
__device__ __half  g_wqkv[3 * CH * CH];
__device__ __half  g_wprj[CH * CH];
__device__ __half  g_wm1 [HID * CH];
__device__ __half  g_wm2 [CH * HID];

// ---------------- helpers ----------------
__device__ __forceinline__ uint32_t smem_u32(const void* p) {
    uint32_t a;
    asm("{ .reg .u64 t; cvta.to.shared.u64 t, %1; cvt.u32.u64 %0, t; }" : "=r"(a) : "l"(p));
    return a;
}

__device__ __forceinline__ void ldm_x4(uint32_t* r, uint32_t addr) {
    asm volatile("ldmatrix.sync.aligned.m8n8.x4.shared.b16 {%0,%1,%2,%3}, [%4];"
                 : "=r"(r[0]), "=r"(r[1]), "=r"(r[2]), "=r"(r[3]) : "r"(addr));
}

__device__ __forceinline__ void mma_bf16(float* d, const uint32_t* a, uint32_t b0, uint32_t b1) {
    asm volatile("mma.sync.aligned.m16n8k16.row.col.f32.bf16.bf16.f32 "
                 "{%0,%1,%2,%3}, {%4,%5,%6,%7}, {%8,%9}, {%0,%1,%2,%3};"
                 : "+f"(d[0]), "+f"(d[1]), "+f"(d[2]), "+f"(d[3])
                 : "r"(a[0]), "r"(a[1]), "r"(a[2]), "r"(a[3]), "r"(b0), "r"(b1));
}

__device__ __forceinline__ void mma_f16(float* d, const uint32_t* a, uint32_t b0, uint32_t b1) {
    asm volatile("mma.sync.aligned.m16n8k16.row.col.f32.f16.f16.f32 "
                 "{%0,%1,%2,%3}, {%4,%5,%6,%7}, {%8,%9}, {%0,%1,%2,%3};"
                 : "+f"(d[0]), "+f"(d[1]), "+f"(d[2]), "+f"(d[3])
                 : "r"(a[0]), "r"(a[1]), "r"(a[2]), "r"(a[3]), "r"(b0), "r"(b1));
}

__device__ __forceinline__ void cp16(uint32_t dst, const void* src) {
    asm volatile("cp.async.cg.shared.global [%0], [%1], 16;" :: "r"(dst), "l"(src));
}

// bf16 split helpers (attention internals)
__device__ __forceinline__ void split_store_b(float v, __nv_bfloat16* ph, __nv_bfloat16* pl) {
    __nv_bfloat16 h = __float2bfloat16(v);
    *ph = h;
    *pl = __float2bfloat16(v - __bfloat162float(h));
}
__device__ __forceinline__ uint32_t pack_bf16(float a, float b) {
    __nv_bfloat162 t(__float2bfloat16(a), __float2bfloat16(b));
    return *reinterpret_cast<uint32_t*>(&t);
}
__device__ __forceinline__ uint32_t pack_bf16_lo(float a, float b, uint32_t hi) {
    __nv_bfloat162 h = *reinterpret_cast<__nv_bfloat162*>(&hi);
    __nv_bfloat16 lx = __float2bfloat16(a - __bfloat162float(h.x));
    __nv_bfloat16 ly = __float2bfloat16(b - __bfloat162float(h.y));
    __nv_bfloat162 t(lx, ly);
    return *reinterpret_cast<uint32_t*>(&t);
}

__device__ __forceinline__ int proj_remap(int grow) {
    int win = grow / 49, tt = grow % 49;
    int bb  = win >> 6, rem = win & 63;
    int ii  = (rem >> 3) * WSZ + tt / WSZ;
    int jj  = (rem & 7)  * WSZ + tt % WSZ;
    int yi  = ii + SHF; if (yi >= HH) yi -= HH;
    int xj  = jj + SHF; if (xj >= WW) xj -= WW;
    return (bb * HH + yi) * WW + xj;
}

// ---------------- fused weight prep: transpose [K,N] -> fp16 [N,K] ----------------
#define WQKV_E (CH * 3 * CH)
#define WPRJ_E (CH * CH)
#define WM1_E  (CH * HID)
#define WM2_E  (HID * CH)
#define WTOT_E (WQKV_E + WPRJ_E + WM1_E + WM2_E)

__global__ void __launch_bounds__(256) wprep_all(
    const float* __restrict__ qkvw, const float* __restrict__ prjw,
    const float* __restrict__ m1w,  const float* __restrict__ m2w,
    __half* __restrict__ wq, __half* __restrict__ wp,
    __half* __restrict__ w1, __half* __restrict__ w2)
{
    int i = blockIdx.x * 256 + threadIdx.x;
    if (i >= WTOT_E) return;
    const float* src; __half* dst; int K, N;
    if (i < WQKV_E)                       { src = qkvw; dst = wq; K = CH;  N = 3 * CH; }
    else if (i < WQKV_E + WPRJ_E)         { i -= WQKV_E;          src = prjw; dst = wp; K = CH;  N = CH; }
    else if (i < WQKV_E + WPRJ_E + WM1_E) { i -= WQKV_E + WPRJ_E; src = m1w;  dst = w1; K = CH;  N = HID; }
    else                                  { i -= WQKV_E + WPRJ_E + WM1_E; src = m2w; dst = w2; K = HID; N = CH; }
    int n = i / K, k = i - n * K;
    dst[i] = __float2half(src[(size_t)k * N + n]);
}

// ---------------- LN (warp per row) writing fp16 ----------------
template<bool GATHER>
__global__ void __launch_bounds__(256) ln_kernel(const float* __restrict__ x,
                                                 const float* __restrict__ w,
                                                 const float* __restrict__ b,
                                                 __half* __restrict__ oh)
{
    int row  = (blockIdx.x * blockDim.x + threadIdx.x) >> 5;
    int lane = threadIdx.x & 31;
    if (row >= TOK) return;

    int src_row;
    if (GATHER) {
        int win = row / 49, t = row % 49;
        int bb  = win >> 6, rem = win & 63;
        int i   = (rem >> 3) * WSZ + t / WSZ;
        int j   = (rem & 7)  * WSZ + t % WSZ;
        int yi  = i + SHF; if (yi >= HH) yi -= HH;
        int xj  = j + SHF; if (xj >= WW) xj -= WW;
        src_row = (bb * HH + yi) * WW + xj;
    } else src_row = row;

    const float* px = x + (size_t)src_row * CH;
    float v[6];
    float s = 0.f, s2 = 0.f;
#pragma unroll
    for (int u = 0; u < 6; u++) { v[u] = px[lane + 32 * u]; s += v[u]; s2 += v[u] * v[u]; }
#pragma unroll
    for (int o = 16; o; o >>= 1) {
        s  += __shfl_xor_sync(0xffffffffu, s,  o);
        s2 += __shfl_xor_sync(0xffffffffu, s2, o);
    }
    float mean = s * (1.f / CH);
    float var  = s2 * (1.f / CH) - mean * mean;
    float rstd = rsqrtf(var + 1e-5f);
#pragma unroll
    for (int u = 0; u < 6; u++) {
        int c = lane + 32 * u;
        oh[(size_t)row * CH + c] = __float2half((v[u] - mean) * rstd * w[c] + b[c]);
    }
}

// ---------------- mma.sync fp16 GEMM: tile M=128 x N=64, K-chunk 64, 1 MMA ----------------
enum { EPI_QKV = 0, EPI_PROJ = 1, EPI_GELU = 2, EPI_ADD = 3 };

#define KP   72
#define STG_A 0u
#define STG_B 18432u
#define STG_BYTES 27648u
#define SMEM_DYN (2 * 27648)

template<int EPI, int NTOT, int KTOT>
__global__ void __launch_bounds__(256) tgemm(
    const __half* __restrict__ A, const __half* __restrict__ B,
    const float* __restrict__ bias,
    float* __restrict__ outf,
    __half* __restrict__ outh,
    const float* __restrict__ res)
{
    extern __shared__ __half S[];
    const uint32_t sbase = smem_u32(S);

    const int tid  = threadIdx.x;
    const int lane = tid & 31, wid = tid >> 5;
    const int wm   = wid & 3,  wn  = wid >> 2;
    const int n0   = blockIdx.x * 64;
    const int m0   = blockIdx.y * 128;

    const uint32_t aOff = (uint32_t)((wm * 32 + (lane & 15)) * KP + (lane >> 4) * 8) * 2;
    const uint32_t bOff = (uint32_t)((wn * 32 + (lane & 7) + ((lane >> 4) << 3)) * KP + ((lane >> 3) & 1) * 8) * 2;

    float acc[2][4][4];
#pragma unroll
    for (int i = 0; i < 2; i++)
#pragma unroll
        for (int j = 0; j < 4; j++)
#pragma unroll
            for (int q = 0; q < 4; q++) acc[i][j][q] = 0.f;

    const int KCH = KTOT / 64;

    auto issue = [&](int kc) {
        const uint32_t so = sbase + (uint32_t)(kc & 1) * STG_BYTES;
        const size_t abase = (size_t)m0 * KTOT + (size_t)kc * 64;
        const size_t bbase = (size_t)n0 * KTOT + (size_t)kc * 64;
#pragma unroll
        for (int i = tid; i < 128 * 8; i += 256) {
            int r = i >> 3, c = i & 7;
            cp16(so + STG_A + (uint32_t)(r * KP + c * 8) * 2, A + abase + (size_t)r * KTOT + c * 8);
        }
#pragma unroll
        for (int i = tid; i < 64 * 8; i += 256) {
            int r = i >> 3, c = i & 7;
            cp16(so + STG_B + (uint32_t)(r * KP + c * 8) * 2, B + bbase + (size_t)r * KTOT + c * 8);
        }
        asm volatile("cp.async.commit_group;" ::: "memory");
    };

    issue(0);

    for (int kc = 0; kc < KCH; kc++) {
        if (kc + 1 < KCH) {
            issue(kc + 1);
            asm volatile("cp.async.wait_group 1;" ::: "memory");
        } else {
            asm volatile("cp.async.wait_group 0;" ::: "memory");
        }
        __syncthreads();

        const uint32_t so = sbase + (uint32_t)(kc & 1) * STG_BYTES;
        const uint32_t adrA0 = so + STG_A + aOff, adrA1 = adrA0 + 16 * KP * 2;
        const uint32_t adrB0 = so + STG_B + bOff, adrB1 = adrB0 + 16 * KP * 2;

#pragma unroll
        for (int ks = 0; ks < 4; ks++) {
            const uint32_t kb = (uint32_t)(ks * 32);
            uint32_t a0[4], a1[4], b0[4], b1[4];
            ldm_x4(a0, adrA0 + kb);
            ldm_x4(a1, adrA1 + kb);
            ldm_x4(b0, adrB0 + kb);
            ldm_x4(b1, adrB1 + kb);

#pragma unroll
            for (int nt = 0; nt < 4; nt++) {
                uint32_t h0 = (nt < 2 ? b0[(nt & 1) * 2]     : b1[(nt & 1) * 2]);
                uint32_t h1 = (nt < 2 ? b0[(nt & 1) * 2 + 1] : b1[(nt & 1) * 2 + 1]);
                mma_f16(acc[0][nt], a0, h0, h1);
                mma_f16(acc[1][nt], a1, h0, h1);
            }
        }
        __syncthreads();
    }

    const int g = lane >> 2, t = lane & 3;
#pragma unroll
    for (int mt = 0; mt < 2; mt++) {
        int r0 = m0 + wm * 32 + mt * 16 + g;
        int r1 = r0 + 8;
        int o0 = r0, o1 = r1;
        if (EPI == EPI_PROJ) { o0 = proj_remap(r0); o1 = proj_remap(r1); }
#pragma unroll
        for (int nt = 0; nt < 4; nt++) {
            int col = n0 + wn * 32 + nt * 8 + 2 * t;
            float b0 = bias[col], b1 = bias[col + 1];
            float v0 = acc[mt][nt][0] + b0, v1 = acc[mt][nt][1] + b1;
            float v2 = acc[mt][nt][2] + b0, v3 = acc[mt][nt][3] + b1;
            if (EPI == EPI_QKV) {
                *(float2*)&outf[(size_t)r0 * NTOT + col] = make_float2(v0, v1);
                *(float2*)&outf[(size_t)r1 * NTOT + col] = make_float2(v2, v3);
            } else if (EPI == EPI_PROJ) {
                const float2 s0 = *(const float2*)&res[(size_t)o0 * NTOT + col];
                const float2 s1 = *(const float2*)&res[(size_t)o1 * NTOT + col];
                *(float2*)&outf[(size_t)o0 * NTOT + col] = make_float2(s0.x + v0, s0.y + v1);
                *(float2*)&outf[(size_t)o1 * NTOT + col] = make_float2(s1.x + v2, s1.y + v3);
            } else if (EPI == EPI_GELU) {
                float g0 = 0.5f * v0 * (1.f + erff(v0 * 0.7071067811865475f));
                float g1 = 0.5f * v1 * (1.f + erff(v1 * 0.7071067811865475f));
                float g2 = 0.5f * v2 * (1.f + erff(v2 * 0.7071067811865475f));
                float g3 = 0.5f * v3 * (1.f + erff(v3 * 0.7071067811865475f));
                *(__half2*)&outh[(size_t)r0 * NTOT + col] = __half2(__float2half(g0), __float2half(g1));
                *(__half2*)&outh[(size_t)r1 * NTOT + col] = __half2(__float2half(g2), __float2half(g3));
            } else { // EPI_ADD
                const float2 s0 = *(const float2*)&res[(size_t)r0 * NTOT + col];
                const float2 s1 = *(const float2*)&res[(size_t)r1 * NTOT + col];
                *(float2*)&outf[(size_t)r0 * NTOT + col] = make_float2(s0.x + v0, s0.y + v1);
                *(float2*)&outf[(size_t)r1 * NTOT + col] = make_float2(s1.x + v2, s1.y + v3);
            }
        }
    }
}

// ---------------- attention (R15 config; internals bf16-split; output single fp16) ----------------
#define QKP 40
#define VTP 72
#define AQH 0u
#define AQL 3920u
#define AKH 7840u
#define AKL 11760u
#define AVH 15680u
#define AVL 20288u
#define ATTN_SMEM 24896

__global__ void __launch_bounds__(128) attn_mma()
{
    extern __shared__ __align__(16) char SM[];
    __nv_bfloat16* sQh = (__nv_bfloat16*)(SM + AQH);
    __nv_bfloat16* sQl = (__nv_bfloat16*)(SM + AQL);
    __nv_bfloat16* sKh = (__nv_bfloat16*)(SM + AKH);
    __nv_bfloat16* sKl = (__nv_bfloat16*)(SM + AKL);
    __nv_bfloat16* sVh = (__nv_bfloat16*)(SM + AVH);
    __nv_bfloat16* sVl = (__nv_bfloat16*)(SM + AVL);

    const int win = blockIdx.x / NHEAD;
    const int h   = blockIdx.x % NHEAD;
    const int tid = threadIdx.x;
    const int lane = tid & 31, w = tid >> 5;

    for (int i = tid; i < 32 * 15; i += 128) {
        int d = i / 15, j = 49 + i % 15;
        sVh[d * VTP + j] = __nv_bfloat16(0.f);
        sVl[d * VTP + j] = __nv_bfloat16(0.f);
    }

    const float scale = 0.17677669529663687f;
    const float* base = g_qkv + (size_t)win * 49 * (3 * CH) + h * 32;
    for (int i = tid; i < 49 * 32; i += 128) {
        int t = i >> 5, d = i & 31;
        const float* p = base + (size_t)t * (3 * CH) + d;
        float qv = p[0] * scale, kv = p[CH], vv = p[2 * CH];
        split_store_b(qv, &sQh[t * QKP + d], &sQl[t * QKP + d]);
        split_store_b(kv, &sKh[t * QKP + d], &sKl[t * QKP + d]);
        split_store_b(vv, &sVh[d * VTP + t], &sVl[d * VTP + t]);
    }
    __syncthreads();

    const uint32_t sb = smem_u32(SM);
    const int g = lane >> 2, t4 = lane & 3;
    const int r0 = w * 16 + g, r1 = r0 + 8;

    float acc[8][4];
#pragma unroll
    for (int i = 0; i < 8; i++)
#pragma unroll
        for (int j = 0; j < 4; j++) acc[i][j] = 0.f;

    {
        const uint32_t aoff = (uint32_t)((w * 16 + (lane & 15)) * QKP + (lane >> 4) * 8) * 2;
        const uint32_t adrQh = sb + AQH + aoff;
        const uint32_t adrQl = sb + AQL + aoff;
        const uint32_t brow  = (uint32_t)((lane & 7) + ((lane >> 4) << 3));
        const uint32_t bcol  = (uint32_t)(((lane >> 3) & 1) * 8);

#pragma unroll
        for (int ks = 0; ks < 2; ks++) {
            const uint32_t kb = (uint32_t)(ks * 32);
            uint32_t qh[4], ql[4];
            ldm_x4(qh, adrQh + kb);
            ldm_x4(ql, adrQl + kb);
#pragma unroll
            for (int nb = 0; nb < 4; nb++) {
                const uint32_t boff = (uint32_t)((nb * 16 + brow) * QKP + bcol) * 2 + kb;
                uint32_t kh[4], kl[4];
                ldm_x4(kh, sb + AKH + boff);
                ldm_x4(kl, sb + AKL + boff);
#pragma unroll
                for (int s = 0; s < 2; s++) {
                    int nt = nb * 2 + s;
                    mma_bf16(acc[nt], qh, kh[s * 2], kh[s * 2 + 1]);
                    mma_bf16(acc[nt], qh, kl[s * 2], kl[s * 2 + 1]);
                    mma_bf16(acc[nt], ql, kh[s * 2], kh[s * 2 + 1]);
                }
            }
        }
    }

    {
        float mx0 = -1e30f, mx1 = -1e30f;
#pragma unroll
        for (int nt = 0; nt < 8; nt++) {
            int col = nt * 8 + 2 * t4;
            if (col < 49)     { mx0 = fmaxf(mx0, acc[nt][0]); mx1 = fmaxf(mx1, acc[nt][2]); }
            if (col + 1 < 49) { mx0 = fmaxf(mx0, acc[nt][1]); mx1 = fmaxf(mx1, acc[nt][3]); }
        }
        mx0 = fmaxf(mx0, __shfl_xor_sync(0xffffffffu, mx0, 1));
        mx0 = fmaxf(mx0, __shfl_xor_sync(0xffffffffu, mx0, 2));
        mx1 = fmaxf(mx1, __shfl_xor_sync(0xffffffffu, mx1, 1));
        mx1 = fmaxf(mx1, __shfl_xor_sync(0xffffffffu, mx1, 2));

        float s0 = 0.f, s1 = 0.f;
#pragma unroll
        for (int nt = 0; nt < 8; nt++) {
            int col = nt * 8 + 2 * t4;
            float e0 = (col < 49)     ? expf(acc[nt][0] - mx0) : 0.f;
            float e1 = (col + 1 < 49) ? expf(acc[nt][1] - mx0) : 0.f;
            float e2 = (col < 49)     ? expf(acc[nt][2] - mx1) : 0.f;
            float e3 = (col + 1 < 49) ? expf(acc[nt][3] - mx1) : 0.f;
            acc[nt][0] = e0; acc[nt][1] = e1; acc[nt][2] = e2; acc[nt][3] = e3;
            s0 += e0 + e1; s1 += e2 + e3;
        }
        s0 += __shfl_xor_sync(0xffffffffu, s0, 1);
        s0 += __shfl_xor_sync(0xffffffffu, s0, 2);
        s1 += __shfl_xor_sync(0xffffffffu, s1, 1);
        s1 += __shfl_xor_sync(0xffffffffu, s1, 2);
        float inv0 = 1.f / s0, inv1 = 1.f / s1;

#pragma unroll
        for (int nt = 0; nt < 8; nt++) {
            acc[nt][0] *= inv0; acc[nt][1] *= inv0;
            acc[nt][2] *= inv1; acc[nt][3] *= inv1;
        }
    }

    {
        const uint32_t brow = (uint32_t)((lane & 7) + ((lane >> 4) << 3));
        const uint32_t bcol = (uint32_t)(((lane >> 3) & 1) * 8);

        float oacc[4][4];
#pragma unroll
        for (int i = 0; i < 4; i++)
#pragma unroll
            for (int j = 0; j < 4; j++) oacc[i][j] = 0.f;

#pragma unroll
        for (int ks = 0; ks < 4; ks++) {
            uint32_t ph[4], pl[4];
            ph[0] = pack_bf16(acc[2 * ks][0],     acc[2 * ks][1]);
            ph[1] = pack_bf16(acc[2 * ks][2],     acc[2 * ks][3]);
            ph[2] = pack_bf16(acc[2 * ks + 1][0], acc[2 * ks + 1][1]);
            ph[3] = pack_bf16(acc[2 * ks + 1][2], acc[2 * ks + 1][3]);
            pl[0] = pack_bf16_lo(acc[2 * ks][0],     acc[2 * ks][1],     ph[0]);
            pl[1] = pack_bf16_lo(acc[2 * ks][2],     acc[2 * ks][3],     ph[1]);
            pl[2] = pack_bf16_lo(acc[2 * ks + 1][0], acc[2 * ks + 1][1], ph[2]);
            pl[3] = pack_bf16_lo(acc[2 * ks + 1][2], acc[2 * ks + 1][3], ph[3]);

            const uint32_t kb = (uint32_t)(ks * 32);
#pragma unroll
            for (int nb = 0; nb < 2; nb++) {
                const uint32_t boff = (uint32_t)((nb * 16 + brow) * VTP + bcol) * 2 + kb;
                uint32_t vh[4], vl[4];
                ldm_x4(vh, sb + AVH + boff);
                ldm_x4(vl, sb + AVL + boff);
#pragma unroll
                for (int s = 0; s < 2; s++) {
                    int nt = nb * 2 + s;
                    mma_bf16(oacc[nt], ph, vh[s * 2], vh[s * 2 + 1]);
                    mma_bf16(oacc[nt], ph, vl[s * 2], vl[s * 2 + 1]);
                    mma_bf16(oacc[nt], pl, vh[s * 2], vh[s * 2 + 1]);
                }
            }
        }

        const size_t ob = (size_t)win * 49 * CH + h * 32;
#pragma unroll
        for (int nt = 0; nt < 4; nt++) {
            int d = nt * 8 + t4 * 2;
            if (r0 < 49)
                *(__half2*)&g_ob[ob + (size_t)r0 * CH + d] =
                    __half2(__float2half(oacc[nt][0]), __float2half(oacc[nt][1]));
            if (r1 < 49)
                *(__half2*)&g_ob[ob + (size_t)r1 * CH + d] =
                    __half2(__float2half(oacc[nt][2]), __float2half(oacc[nt][3]));
        }
    }
}

// ---------------- launch ----------------
extern "C" void kernel_launch(void* const* d_in, const int* in_sizes, int n_in,
                              void* d_out, int out_size)
{
    const float* x      = (const float*)d_in[0];
    const float* ln1_w  = (const float*)d_in[1];
    const float* ln1_b  = (const float*)d_in[2];
    const float* qkv_w  = (const float*)d_in[3];
    const float* qkv_b  = (const float*)d_in[4];
    const float* proj_w = (const float*)d_in[5];
    const float* proj_b = (const float*)d_in[6];
    const float* ln2_w  = (const float*)d_in[7];
    const float* ln2_b  = (const float*)d_in[8];
    const float* mlp_w1 = (const float*)d_in[9];
    const float* mlp_b1 = (const float*)d_in[10];
    const float* mlp_w2 = (const float*)d_in[11];
    const float* mlp_b2 = (const float*)d_in[12];
    float* out = (float*)d_out;

    float *p_qkv, *p_x1;
    __half *p_xw, *p_ob, *p_hin, *p_h;
    __half *p_wqkv, *p_wprj, *p_wm1, *p_wm2;
    cudaGetSymbolAddress((void**)&p_qkv,  g_qkv);
    cudaGetSymbolAddress((void**)&p_x1,   g_x1);
    cudaGetSymbolAddress((void**)&p_xw,   g_xw);
    cudaGetSymbolAddress((void**)&p_ob,   g_ob);
    cudaGetSymbolAddress((void**)&p_hin,  g_hin);
    cudaGetSymbolAddress((void**)&p_h,    g_h);
    cudaGetSymbolAddress((void**)&p_wqkv, g_wqkv);
    cudaGetSymbolAddress((void**)&p_wprj, g_wprj);
    cudaGetSymbolAddress((void**)&p_wm1,  g_wm1);
    cudaGetSymbolAddress((void**)&p_wm2,  g_wm2);

    cudaFuncSetAttribute(tgemm<EPI_QKV, 576, 192>,  cudaFuncAttributeMaxDynamicSharedMemorySize, SMEM_DYN);
    cudaFuncSetAttribute(tgemm<EPI_PROJ, 192, 192>, cudaFuncAttributeMaxDynamicSharedMemorySize, SMEM_DYN);
    cudaFuncSetAttribute(tgemm<EPI_GELU, 768, 192>, cudaFuncAttributeMaxDynamicSharedMemorySize, SMEM_DYN);
    cudaFuncSetAttribute(tgemm<EPI_ADD, 192, 768>,  cudaFuncAttributeMaxDynamicSharedMemorySize, SMEM_DYN);
    cudaFuncSetAttribute(attn_mma, cudaFuncAttributeMaxDynamicSharedMemorySize, ATTN_SMEM);

    wprep_all<<<(WTOT_E + 255) / 256, 256>>>(qkv_w, proj_w, mlp_w1, mlp_w2,
                                             p_wqkv, p_wprj, p_wm1, p_wm2);

    const int LN_BLOCKS = TOK / 8;

    // 1. LN1 + shift + window partition
    ln_kernel<true><<<LN_BLOCKS, 256>>>(x, ln1_w, ln1_b, p_xw);

    // 2. qkv GEMM [50176 x 576], K=192
    tgemm<EPI_QKV, 576, 192><<<dim3(9, TOK / 128), 256, SMEM_DYN>>>(
        p_xw, p_wqkv, qkv_b, p_qkv, nullptr, nullptr);

    // 3. windowed attention
    attn_mma<<<NWIN * NHEAD, 128, ATTN_SMEM>>>();

    // 4. proj GEMM + window reverse + unshift + shortcut
    tgemm<EPI_PROJ, 192, 192><<<dim3(3, TOK / 128), 256, SMEM_DYN>>>(
        p_ob, p_wprj, proj_b, p_x1, nullptr, x);

    // 5. LN2
    ln_kernel<false><<<LN_BLOCKS, 256>>>(p_x1, ln2_w, ln2_b, p_hin);

    // 6. mlp1 + GELU
    tgemm<EPI_GELU, 768, 192><<<dim3(12, TOK / 128), 256, SMEM_DYN>>>(
        p_hin, p_wm1, mlp_b1, nullptr, p_h, nullptr);

    // 7. mlp2 + residual
    tgemm<EPI_ADD, 192, 768><<<dim3(3, TOK / 128), 256, SMEM_DYN>>>(
        p_h, p_wm2, mlp_b2, out, nullptr, p_x1);
}